// round 11
// baseline (speedup 1.0000x reference)
#include <cuda_runtime.h>

#define HH 56
#define WW 56
#define HW 3136
#define NB 16
#define NFM 32
#define NC 128

// ---------------- device scratch ----------------
__device__ float g_Ab[NB * NC * HW];
__device__ float g_sum[NB * NC];
__device__ int   g_fmidx[NB * NFM];
__device__ float g_Kch[NC * NC * 25];
__device__ float g_W2[NC * NC * 25];
__device__ float g_Pad[NB][NFM][3600];   // padded (60x60) winner channels, tf32-rounded

__device__ __forceinline__ int map2i(int i) { return i < 2 ? 3 - i : (i >= 54 ? 107 - i : i); }
__device__ __forceinline__ int mPad(int i)  { return i < 4 ? 5 - i : (i < 56 ? i - 2 : 109 - i); }

__device__ __forceinline__ float tf32r(float x) {
    float r; asm("cvt.rna.tf32.f32 %0, %1;" : "=f"(r) : "f"(x)); return r;
}
__device__ __forceinline__ void cp8(unsigned dst, const float* src) {
    asm volatile("cp.async.ca.shared.global [%0], [%1], 8;" ::
                 "r"(dst), "l"(__cvta_generic_to_global(src)));
}
__device__ __forceinline__ void cp16(unsigned dst, const float* src) {
    asm volatile("cp.async.cg.shared.global [%0], [%1], 16;" ::
                 "r"(dst), "l"(__cvta_generic_to_global(src)));
}
__device__ __forceinline__ void cp_commit() { asm volatile("cp.async.commit_group;"); }

__device__ __forceinline__ void mma_tf32(float* d, unsigned a0, unsigned a1, unsigned a2,
                                         unsigned a3, unsigned b0, unsigned b1) {
    asm volatile("mma.sync.aligned.m16n8k8.row.col.f32.tf32.tf32.f32 "
                 "{%0,%1,%2,%3}, {%4,%5,%6,%7}, {%8,%9}, {%0,%1,%2,%3};"
                 : "+f"(d[0]), "+f"(d[1]), "+f"(d[2]), "+f"(d[3])
                 : "r"(a0), "r"(a1), "r"(a2), "r"(a3), "r"(b0), "r"(b1));
}

// ---------------- kernel 0: zero K_change ----------------
__global__ void k_zero() { g_Kch[blockIdx.x * 1024 + threadIdx.x] = 0.0f; }

// ---------------- kernel 1: Ab + per-map sums (smem-staged A, float4 streams) ----------------
__global__ __launch_bounds__(256) void k_ab(const float* __restrict__ A,
                                            const float* __restrict__ noise) {
    __shared__ float sA[HW];
    __shared__ float red[8];
    int bf = blockIdx.x;             // b*32 + fm
    int b = bf >> 5, fm = bf & 31;
    const float4* a4 = (const float4*)(A + (size_t)(b * NFM + fm) * HW);
    for (int p = threadIdx.x; p < 784; p += 256) ((float4*)sA)[p] = a4[p];
    __syncthreads();
    for (int r = 0; r < 4; r++) {
        int c = r * NFM + fm;
        const float4* n4 = (const float4*)(noise + ((size_t)b * NC + c) * HW);
        float4* o4 = (float4*)(g_Ab + ((size_t)b * NC + c) * HW);
        float s = 0.0f;
        for (int p = threadIdx.x; p < 784; p += 256) {
            float4 nv = n4[p];
            int pix = p * 4;
            int h = (pix * 37450) >> 21;     // pix / 56
            int w = pix - h * WW;            // w <= 52, so w..w+3 same row
            int hm = map2i(h) * WW;
            float4 v;
            v.x = fmaxf(sA[hm + map2i(w)]     + 0.1f * nv.x, 0.0f);
            v.y = fmaxf(sA[hm + map2i(w + 1)] + 0.1f * nv.y, 0.0f);
            v.z = fmaxf(sA[hm + map2i(w + 2)] + 0.1f * nv.z, 0.0f);
            v.w = fmaxf(sA[hm + map2i(w + 3)] + 0.1f * nv.w, 0.0f);
            o4[p] = v;
            s += v.x + v.y + v.z + v.w;
        }
        #pragma unroll
        for (int o = 16; o; o >>= 1) s += __shfl_xor_sync(0xffffffffu, s, o);
        if ((threadIdx.x & 31) == 0) red[threadIdx.x >> 5] = s;
        __syncthreads();
        if (threadIdx.x == 0) {
            float t = 0.0f;
            #pragma unroll
            for (int i = 0; i < 8; i++) t += red[i];
            g_sum[b * NC + c] = t;
        }
        __syncthreads();
    }
}

// ---------------- kernel 2: winners + padded winner channels (fused) ----------------
__global__ __launch_bounds__(256) void k_pad() {
    int b = blockIdx.x, j = blockIdx.y;
    // every thread recomputes the argmax (4 loads, L2-hot)
    const float* s = g_sum + b * NC;
    float best = s[j];
    int wi = 0;
    #pragma unroll
    for (int r = 1; r < 4; r++) {
        float v = s[r * NFM + j];
        if (v > best) { best = v; wi = r; }
    }
    int c = wi * NFM + j;
    if (threadIdx.x == 0) g_fmidx[b * NFM + j] = c;
    const float* src = g_Ab + (size_t)(b * NC + c) * HW;
    float* dst = &g_Pad[b][j][0];
    for (int p = threadIdx.x; p < 3600; p += 256) {
        int r = p / 60, w = p - r * 60;
        dst[p] = tf32r(src[mPad(r) * WW + mPad(w)]);
    }
}

// ---------------- kernel 3: K_change via tf32 mma.sync ----------------
#define AM_STRIDE 230
#define AM_FLTS  (32 * AM_STRIDE)
#define AB_STRIDE 480
#define AB_FLTS  (8 * AB_STRIDE)
#define KC_SMEM  ((2 * AM_FLTS + 2 * AB_FLTS) * 4)

__device__ __forceinline__ void kc_load_chunk(float* smA, float* smB, const float* abB,
                                              const int* sWin, int aBase, int cc, int tid) {
    unsigned dA = (unsigned)__cvta_generic_to_shared(smA);
    #pragma unroll
    for (int t = 0; t < 14; t++) {
        int idx = tid + t * 256;
        int j = idx / 112;
        int rem = idx - j * 112;
        int r = rem / 28, w = (rem - r * 28) * 2;
        cp8(dA + (unsigned)((j * AM_STRIDE + r * 56 + w) * 4),
            abB + (size_t)sWin[j] * HW + (cc * 4 + r) * WW + w);
    }
    unsigned dB = (unsigned)__cvta_generic_to_shared(smB);
    #pragma unroll
    for (int t = 0; t < 7; t++) {
        int idx = tid + t * 256;
        int a = idx / 224;
        int rem = idx - a * 224;
        int rr = rem / 28, w = (rem - rr * 28) * 2;
        int g = cc * 4 + rr;
        unsigned off = (unsigned)((a * AB_STRIDE + rr * 60 + 2 + w) * 4);
        if (g >= 2 && g <= 57) {
            cp8(dB + off, abB + (size_t)(aBase + a) * HW + (g - 2) * WW + w);
        } else {
            *(float2*)(smB + a * AB_STRIDE + rr * 60 + 2 + w) = make_float2(0.f, 0.f);
        }
    }
}

__global__ __launch_bounds__(256, 2) void k_kchange() {
    extern __shared__ __align__(16) float dyn[];
    float* smA = dyn;
    float* smB = dyn + 2 * AM_FLTS;
    __shared__ int sWin[32];
    int atile = blockIdx.x, b = blockIdx.y;
    int tid = threadIdx.x, wid = tid >> 5, lane = tid & 31;
    int gid = lane >> 2, tig = lane & 3;
    if (tid < 32) sWin[tid] = g_fmidx[b * NFM + tid];
    for (int p = tid; p < 2 * AM_FLTS + 2 * AB_FLTS; p += 256) dyn[p] = 0.f;
    __syncthreads();
    const float* abB = g_Ab + (size_t)(b * NC) * HW;
    int aBase = atile * 8;
    int cbs[4];
    #pragma unroll
    for (int jt = 0; jt < 4; jt++) {
        int xy = jt * 8 + gid; if (xy > 24) xy = 24;
        int x = xy / 5, y = xy - x * 5;
        cbs[jt] = (4 - x) * 60 + (4 - y);
    }
    float d[2][4][4];
    #pragma unroll
    for (int m = 0; m < 2; m++)
        #pragma unroll
        for (int jt = 0; jt < 4; jt++)
            #pragma unroll
            for (int q = 0; q < 4; q++) d[m][jt][q] = 0.f;

    kc_load_chunk(smA, smB, abB, sWin, aBase, 0, tid);
    cp_commit();
    int aOff0 = gid * AM_STRIDE + tig;
    for (int cc = 0; cc < 14; cc++) {
        int st = cc & 1;
        if (cc + 1 < 14) {
            kc_load_chunk(smA + (st ^ 1) * AM_FLTS, smB + (st ^ 1) * AB_FLTS,
                          abB, sWin, aBase, cc + 1, tid);
            cp_commit();
            asm volatile("cp.async.wait_group 1;" ::: "memory");
        } else {
            asm volatile("cp.async.wait_group 0;" ::: "memory");
        }
        __syncthreads();
        const float* Ax = smA + st * AM_FLTS;
        const float* Bx = smB + st * AB_FLTS + wid * AB_STRIDE;
        #pragma unroll
        for (int rl = 0; rl < 4; rl++) {
            #pragma unroll
            for (int ws = 0; ws < 7; ws++) {
                int ao = aOff0 + rl * 56 + ws * 8;
                int bo = rl * 60 + ws * 8 + tig;
                unsigned a0 = __float_as_uint(Ax[ao]);
                unsigned a1 = __float_as_uint(Ax[ao + 8 * AM_STRIDE]);
                unsigned a2 = __float_as_uint(Ax[ao + 4]);
                unsigned a3 = __float_as_uint(Ax[ao + 8 * AM_STRIDE + 4]);
                unsigned a4 = __float_as_uint(Ax[ao + 16 * AM_STRIDE]);
                unsigned a5 = __float_as_uint(Ax[ao + 24 * AM_STRIDE]);
                unsigned a6 = __float_as_uint(Ax[ao + 16 * AM_STRIDE + 4]);
                unsigned a7 = __float_as_uint(Ax[ao + 24 * AM_STRIDE + 4]);
                #pragma unroll
                for (int jt = 0; jt < 4; jt++) {
                    unsigned b0 = __float_as_uint(Bx[cbs[jt] + bo]);
                    unsigned b1 = __float_as_uint(Bx[cbs[jt] + bo + 4]);
                    mma_tf32(d[0][jt], a0, a1, a2, a3, b0, b1);
                    mma_tf32(d[1][jt], a4, a5, a6, a7, b0, b1);
                }
            }
        }
        __syncthreads();
    }
    int aCh = aBase + wid;
    #pragma unroll
    for (int m = 0; m < 2; m++) {
        int c0 = sWin[m * 16 + gid];
        int c1 = sWin[m * 16 + gid + 8];
        #pragma unroll
        for (int jt = 0; jt < 4; jt++) {
            int xy0 = jt * 8 + tig * 2;
            if (xy0 < 25) {
                atomicAdd(g_Kch + c0 * 3200 + aCh * 25 + xy0, d[m][jt][0]);
                atomicAdd(g_Kch + c1 * 3200 + aCh * 25 + xy0, d[m][jt][2]);
            }
            if (xy0 + 1 < 25) {
                atomicAdd(g_Kch + c0 * 3200 + aCh * 25 + xy0 + 1, d[m][jt][1]);
                atomicAdd(g_Kch + c1 * 3200 + aCh * 25 + xy0 + 1, d[m][jt][3]);
            }
        }
    }
}

// ---------------- kernel 4: combine weights (tf32-rounded output) ----------------
__global__ __launch_bounds__(256) void k_combine(const float* __restrict__ K) {
    int t = blockIdx.x * 256 + threadIdx.x;
    int o = t >> 7, i = t & 127;
    const float* kc = g_Kch + (i * NC + o) * 25;
    const float* kk = K + (o * NC + i) * 25;
    float v[25];
    float mn = 1e30f, mx = -1e30f;
    #pragma unroll
    for (int s = 0; s < 25; s++) {
        v[s] = kc[s] * (1.0f / 2048.0f);
        mn = fminf(mn, v[s]); mx = fmaxf(mx, v[s]);
    }
    float inv = 1.0f / (mx - mn + 1e-10f);
    float mn2 = 1e30f, mx2 = -1e30f;
    #pragma unroll
    for (int s = 0; s < 25; s++) {
        v[s] = 0.9f * kk[s] + 0.1f * ((v[s] - mn) * inv);
        mn2 = fminf(mn2, v[s]); mx2 = fmaxf(mx2, v[s]);
    }
    float inv2 = 1.0f / (mx2 - mn2 + 1e-10f);
    float* dst = g_W2 + (o * NC + i) * 25;
    #pragma unroll
    for (int s = 0; s < 25; s++) dst[s] = tf32r((v[s] - mn2) * inv2);
}

// ---------------- kernel 5: L2 conv + output via tf32 mma ----------------
// A fragments loaded directly from g_W2 (tf32-rounded, k<25 predicated); B strip in smem.
__global__ __launch_bounds__(128, 4) void k_l2mma(float* __restrict__ out) {
    __shared__ __align__(16) float sP[2][480];   // 8 pad rows x 60
    __shared__ int wl[32];
    int q = blockIdx.x, b = blockIdx.y;
    int tid = threadIdx.x, wid = tid >> 5, lane = tid & 31;
    int gid = lane >> 2, tig = lane & 3;
    if (tid < 32) wl[tid] = g_fmidx[b * NFM + tid];
    __syncthreads();

    int offk[4][2];
    #pragma unroll
    for (int ks = 0; ks < 4; ks++) {
        #pragma unroll
        for (int hh = 0; hh < 2; hh++) {
            int xy = ks * 8 + tig + hh * 4; if (xy > 24) xy = 24;
            int kx = xy / 5, ky = xy - kx * 5;
            offk[ks][hh] = kx * 60 + ky;
        }
    }
    // per-thread W2 row bases (constant over i): rows fm = gid, gid+8, 16+gid, 24+gid
    const float* wrow[4];
    #pragma unroll
    for (int mr = 0; mr < 4; mr++)
        wrow[mr] = g_W2 + (size_t)wl[(mr >> 1) * 16 + (mr & 1) * 8 + gid] * (NC * 25);

    int ntBeg = wid * 7;           // 28 n-tiles, 7 per warp
    float acc[7][2][4];
    #pragma unroll
    for (int j = 0; j < 7; j++)
        #pragma unroll
        for (int m = 0; m < 2; m++)
            #pragma unroll
            for (int v = 0; v < 4; v++) acc[j][m][v] = 0.f;

    {   // preload B for i = 0
        unsigned dP = (unsigned)__cvta_generic_to_shared(&sP[0][0]);
        const float* src = &g_Pad[b][0][0] + q * 240;
        for (int idx = tid; idx < 120; idx += 128)
            cp16(dP + (unsigned)(idx * 16), src + idx * 4);
        cp_commit();
    }
    for (int i = 0; i < 32; i++) {
        int st = i & 1;
        // A fragments: direct LDG, k>=25 -> 0 (issue before waiting on B)
        int io = wl[i] * 25;
        unsigned aF[2][4][4];
        #pragma unroll
        for (int ks = 0; ks < 4; ks++) {
            int k0 = ks * 8 + tig, k1 = k0 + 4;
            #pragma unroll
            for (int mt = 0; mt < 2; mt++) {
                const float* r0 = wrow[mt * 2] + io;
                const float* r1 = wrow[mt * 2 + 1] + io;
                aF[mt][ks][0] = __float_as_uint(k0 < 25 ? r0[k0] : 0.f);
                aF[mt][ks][1] = __float_as_uint(k0 < 25 ? r1[k0] : 0.f);
                aF[mt][ks][2] = __float_as_uint(k1 < 25 ? r0[k1] : 0.f);
                aF[mt][ks][3] = __float_as_uint(k1 < 25 ? r1[k1] : 0.f);
            }
        }
        if (i + 1 < 32) {
            unsigned dP = (unsigned)__cvta_generic_to_shared(&sP[st ^ 1][0]);
            const float* src = &g_Pad[b][i + 1][0] + q * 240;
            for (int idx = tid; idx < 120; idx += 128)
                cp16(dP + (unsigned)(idx * 16), src + idx * 4);
            cp_commit();
            asm volatile("cp.async.wait_group 1;" ::: "memory");
        } else {
            asm volatile("cp.async.wait_group 0;" ::: "memory");
        }
        __syncthreads();
        const float* Pz = &sP[st][0];
        #pragma unroll
        for (int j = 0; j < 7; j++) {
            int lp = (ntBeg + j) * 8 + gid;        // 0..223
            int r = (lp * 1171) >> 16;             // lp / 56
            int base = lp + r * 4;                 // r*60 + (lp - r*56)
            #pragma unroll
            for (int ks = 0; ks < 4; ks++) {
                unsigned b0 = __float_as_uint(Pz[base + offk[ks][0]]);
                unsigned b1 = __float_as_uint(Pz[base + offk[ks][1]]);
                mma_tf32(acc[j][0], aF[0][ks][0], aF[0][ks][1], aF[0][ks][2],
                         aF[0][ks][3], b0, b1);
                mma_tf32(acc[j][1], aF[1][ks][0], aF[1][ks][1], aF[1][ks][2],
                         aF[1][ks][3], b0, b1);
            }
        }
        __syncthreads();
    }
    const float cmul = 0.1f / 32.0f;
    #pragma unroll
    for (int j = 0; j < 7; j++) {
        int p = q * 224 + (ntBeg + j) * 8 + tig * 2;
        #pragma unroll
        for (int mt = 0; mt < 2; mt++) {
            int fm0 = mt * 16 + gid, fm1 = fm0 + 8;
            const float* ab0 = g_Ab + ((size_t)b * NC + wl[fm0]) * HW;
            const float* ab1 = g_Ab + ((size_t)b * NC + wl[fm1]) * HW;
            float* o0 = out + ((size_t)b * NFM + fm0) * HW;
            float* o1 = out + ((size_t)b * NFM + fm1) * HW;
            o0[p]     = ab0[p]     + cmul * acc[j][mt][0];
            o0[p + 1] = ab0[p + 1] + cmul * acc[j][mt][1];
            o1[p]     = ab1[p]     + cmul * acc[j][mt][2];
            o1[p + 1] = ab1[p + 1] + cmul * acc[j][mt][3];
        }
    }
}

extern "C" void kernel_launch(void* const* d_in, const int* in_sizes, int n_in,
                              void* d_out, int out_size) {
    const float* A     = (const float*)d_in[0];
    const float* K     = (const float*)d_in[1];
    const float* noise = (const float*)d_in[2];
    float* out = (float*)d_out;

    cudaFuncSetAttribute(k_kchange, cudaFuncAttributeMaxDynamicSharedMemorySize, KC_SMEM);

    k_zero<<<400, 1024>>>();
    k_ab<<<512, 256>>>(A, noise);
    k_pad<<<dim3(16, 32), 256>>>();
    k_kchange<<<dim3(16, 16), 256, KC_SMEM>>>();
    k_combine<<<64, 256>>>(K);
    k_l2mma<<<dim3(14, 16), 128>>>(out);
}

// round 12
// speedup vs baseline: 1.1417x; 1.1417x over previous
#include <cuda_runtime.h>

#define HH 56
#define WW 56
#define HW 3136
#define NB 16
#define NFM 32
#define NC 128

// ---------------- device scratch ----------------
__device__ float g_Ab[NB * NC * HW];
__device__ float g_sum[NB * NC];
__device__ int   g_fmidx[NB * NFM];
__device__ float g_Kch[NC * NC * 25];
__device__ float g_W2[NC * NC * 25];
__device__ float g_Pad[NB][NFM][3600];   // padded (60x60) winner channels, tf32-rounded

__device__ __forceinline__ int map2i(int i) { return i < 2 ? 3 - i : (i >= 54 ? 107 - i : i); }
__device__ __forceinline__ int mPad(int i)  { return i < 4 ? 5 - i : (i < 56 ? i - 2 : 109 - i); }

__device__ __forceinline__ float tf32r(float x) {
    float r; asm("cvt.rna.tf32.f32 %0, %1;" : "=f"(r) : "f"(x)); return r;
}
__device__ __forceinline__ void cp4(unsigned dst, const float* src) {
    asm volatile("cp.async.ca.shared.global [%0], [%1], 4;" ::
                 "r"(dst), "l"(__cvta_generic_to_global(src)));
}
__device__ __forceinline__ void cp8(unsigned dst, const float* src) {
    asm volatile("cp.async.ca.shared.global [%0], [%1], 8;" ::
                 "r"(dst), "l"(__cvta_generic_to_global(src)));
}
__device__ __forceinline__ void cp16(unsigned dst, const float* src) {
    asm volatile("cp.async.cg.shared.global [%0], [%1], 16;" ::
                 "r"(dst), "l"(__cvta_generic_to_global(src)));
}
__device__ __forceinline__ void cp_commit() { asm volatile("cp.async.commit_group;"); }

__device__ __forceinline__ void mma_tf32(float* d, unsigned a0, unsigned a1, unsigned a2,
                                         unsigned a3, unsigned b0, unsigned b1) {
    asm volatile("mma.sync.aligned.m16n8k8.row.col.f32.tf32.tf32.f32 "
                 "{%0,%1,%2,%3}, {%4,%5,%6,%7}, {%8,%9}, {%0,%1,%2,%3};"
                 : "+f"(d[0]), "+f"(d[1]), "+f"(d[2]), "+f"(d[3])
                 : "r"(a0), "r"(a1), "r"(a2), "r"(a3), "r"(b0), "r"(b1));
}

// ---------------- kernel 0: zero K_change ----------------
__global__ void k_zero() { g_Kch[blockIdx.x * 1024 + threadIdx.x] = 0.0f; }

// ---------------- kernel 1: Ab + per-map sums ----------------
__global__ __launch_bounds__(256) void k_ab(const float* __restrict__ A,
                                            const float* __restrict__ noise) {
    __shared__ float sA[HW];
    __shared__ float red[8];
    int bf = blockIdx.x;             // b*32 + fm
    int b = bf >> 5, fm = bf & 31;
    const float4* a4 = (const float4*)(A + (size_t)(b * NFM + fm) * HW);
    for (int p = threadIdx.x; p < 784; p += 256) ((float4*)sA)[p] = a4[p];
    __syncthreads();
    for (int r = 0; r < 4; r++) {
        int c = r * NFM + fm;
        const float4* n4 = (const float4*)(noise + ((size_t)b * NC + c) * HW);
        float4* o4 = (float4*)(g_Ab + ((size_t)b * NC + c) * HW);
        float s = 0.0f;
        for (int p = threadIdx.x; p < 784; p += 256) {
            float4 nv = n4[p];
            int pix = p * 4;
            int h = (pix * 37450) >> 21;     // pix / 56
            int w = pix - h * WW;
            int hm = map2i(h) * WW;
            float4 v;
            v.x = fmaxf(sA[hm + map2i(w)]     + 0.1f * nv.x, 0.0f);
            v.y = fmaxf(sA[hm + map2i(w + 1)] + 0.1f * nv.y, 0.0f);
            v.z = fmaxf(sA[hm + map2i(w + 2)] + 0.1f * nv.z, 0.0f);
            v.w = fmaxf(sA[hm + map2i(w + 3)] + 0.1f * nv.w, 0.0f);
            o4[p] = v;
            s += v.x + v.y + v.z + v.w;
        }
        #pragma unroll
        for (int o = 16; o; o >>= 1) s += __shfl_xor_sync(0xffffffffu, s, o);
        if ((threadIdx.x & 31) == 0) red[threadIdx.x >> 5] = s;
        __syncthreads();
        if (threadIdx.x == 0) {
            float t = 0.0f;
            #pragma unroll
            for (int i = 0; i < 8; i++) t += red[i];
            g_sum[b * NC + c] = t;
        }
        __syncthreads();
    }
}

// ---------------- kernel 2: winners + padded winner channels (fused) ----------------
__global__ __launch_bounds__(256) void k_pad() {
    int b = blockIdx.x, j = blockIdx.y;
    const float* s = g_sum + b * NC;
    float best = s[j];
    int wi = 0;
    #pragma unroll
    for (int r = 1; r < 4; r++) {
        float v = s[r * NFM + j];
        if (v > best) { best = v; wi = r; }
    }
    int c = wi * NFM + j;
    if (threadIdx.x == 0) g_fmidx[b * NFM + j] = c;
    const float* src = g_Ab + (size_t)(b * NC + c) * HW;
    float* dst = &g_Pad[b][j][0];
    for (int p = threadIdx.x; p < 3600; p += 256) {
        int r = p / 60, w = p - r * 60;
        dst[p] = tf32r(src[mPad(r) * WW + mPad(w)]);
    }
}

// ---------------- kernel 3: K_change via tf32 mma.sync (k-permuted float2 frags) ----------------
#define AM_STRIDE 232                         // == 8 (mod 32): conflict-free float2 A loads
#define AM_FLTS  (32 * AM_STRIDE)
#define AB_STRIDE 480
#define AB_FLTS  (8 * AB_STRIDE)
#define KC_SMEM  ((2 * AM_FLTS + 2 * AB_FLTS) * 4)

__device__ __forceinline__ void kc_load_chunk(float* smA, float* smB, const float* abB,
                                              const int* sWin, int aBase, int cc, int tid) {
    unsigned dA = (unsigned)__cvta_generic_to_shared(smA);
    #pragma unroll
    for (int t = 0; t < 14; t++) {
        int idx = tid + t * 256;
        int j = idx / 112;
        int rem = idx - j * 112;
        int r = rem / 28, w = (rem - r * 28) * 2;
        cp8(dA + (unsigned)((j * AM_STRIDE + r * 56 + w) * 4),
            abB + (size_t)sWin[j] * HW + (cc * 4 + r) * WW + w);
    }
    unsigned dB = (unsigned)__cvta_generic_to_shared(smB);
    #pragma unroll
    for (int t = 0; t < 7; t++) {
        int idx = tid + t * 256;
        int a = idx / 224;
        int rem = idx - a * 224;
        int rr = rem / 28, w = (rem - rr * 28) * 2;
        int g = cc * 4 + rr;
        unsigned off = (unsigned)((a * AB_STRIDE + rr * 60 + 2 + w) * 4);
        if (g >= 2 && g <= 57) {
            cp8(dB + off, abB + (size_t)(aBase + a) * HW + (g - 2) * WW + w);
        } else {
            *(float2*)(smB + a * AB_STRIDE + rr * 60 + 2 + w) = make_float2(0.f, 0.f);
        }
    }
}

__global__ __launch_bounds__(256, 2) void k_kchange() {
    extern __shared__ __align__(16) float dyn[];
    float* smA = dyn;
    float* smB = dyn + 2 * AM_FLTS;
    __shared__ int sWin[32];
    int atile = blockIdx.x, b = blockIdx.y;
    int tid = threadIdx.x, wid = tid >> 5, lane = tid & 31;
    int gid = lane >> 2, tig = lane & 3;
    if (tid < 32) sWin[tid] = g_fmidx[b * NFM + tid];
    for (int p = tid; p < 2 * AM_FLTS + 2 * AB_FLTS; p += 256) dyn[p] = 0.f;
    __syncthreads();
    const float* abB = g_Ab + (size_t)(b * NC) * HW;
    int aBase = atile * 8;
    int cbs[4];
    #pragma unroll
    for (int jt = 0; jt < 4; jt++) {
        int xy = jt * 8 + gid; if (xy > 24) xy = 24;
        int x = xy / 5, y = xy - x * 5;
        cbs[jt] = (4 - x) * 60 + (4 - y);
    }
    float d[2][4][4];
    #pragma unroll
    for (int m = 0; m < 2; m++)
        #pragma unroll
        for (int jt = 0; jt < 4; jt++)
            #pragma unroll
            for (int q = 0; q < 4; q++) d[m][jt][q] = 0.f;

    kc_load_chunk(smA, smB, abB, sWin, aBase, 0, tid);
    cp_commit();
    // k-permutation: fragment k=tig -> pixel 2*tig, k=tig+4 -> pixel 2*tig+1
    int aOff0 = gid * AM_STRIDE + 2 * tig;
    for (int cc = 0; cc < 14; cc++) {
        int st = cc & 1;
        if (cc + 1 < 14) {
            kc_load_chunk(smA + (st ^ 1) * AM_FLTS, smB + (st ^ 1) * AB_FLTS,
                          abB, sWin, aBase, cc + 1, tid);
            cp_commit();
            asm volatile("cp.async.wait_group 1;" ::: "memory");
        } else {
            asm volatile("cp.async.wait_group 0;" ::: "memory");
        }
        __syncthreads();
        const float* Ax = smA + st * AM_FLTS;
        const float* Bx = smB + st * AB_FLTS + wid * AB_STRIDE;
        #pragma unroll
        for (int rl = 0; rl < 4; rl++) {
            #pragma unroll
            for (int ws = 0; ws < 7; ws++) {
                int ao = aOff0 + rl * 56 + ws * 8;
                float2 A0 = *(const float2*)(Ax + ao);                    // row gid
                float2 A1 = *(const float2*)(Ax + ao + 8 * AM_STRIDE);    // row gid+8
                float2 A2 = *(const float2*)(Ax + ao + 16 * AM_STRIDE);
                float2 A3 = *(const float2*)(Ax + ao + 24 * AM_STRIDE);
                int bo = rl * 60 + ws * 8 + 2 * tig;
                #pragma unroll
                for (int jt = 0; jt < 4; jt++) {
                    unsigned b0 = __float_as_uint(Bx[cbs[jt] + bo]);
                    unsigned b1 = __float_as_uint(Bx[cbs[jt] + bo + 1]);
                    mma_tf32(d[0][jt], __float_as_uint(A0.x), __float_as_uint(A1.x),
                             __float_as_uint(A0.y), __float_as_uint(A1.y), b0, b1);
                    mma_tf32(d[1][jt], __float_as_uint(A2.x), __float_as_uint(A3.x),
                             __float_as_uint(A2.y), __float_as_uint(A3.y), b0, b1);
                }
            }
        }
        __syncthreads();
    }
    int aCh = aBase + wid;
    #pragma unroll
    for (int m = 0; m < 2; m++) {
        int c0 = sWin[m * 16 + gid];
        int c1 = sWin[m * 16 + gid + 8];
        #pragma unroll
        for (int jt = 0; jt < 4; jt++) {
            int xy0 = jt * 8 + tig * 2;
            if (xy0 < 25) {
                atomicAdd(g_Kch + c0 * 3200 + aCh * 25 + xy0, d[m][jt][0]);
                atomicAdd(g_Kch + c1 * 3200 + aCh * 25 + xy0, d[m][jt][2]);
            }
            if (xy0 + 1 < 25) {
                atomicAdd(g_Kch + c0 * 3200 + aCh * 25 + xy0 + 1, d[m][jt][1]);
                atomicAdd(g_Kch + c1 * 3200 + aCh * 25 + xy0 + 1, d[m][jt][3]);
            }
        }
    }
}

// ---------------- kernel 4: combine weights (tf32-rounded output) ----------------
__global__ __launch_bounds__(256) void k_combine(const float* __restrict__ K) {
    int t = blockIdx.x * 256 + threadIdx.x;
    int o = t >> 7, i = t & 127;
    const float* kc = g_Kch + (i * NC + o) * 25;
    const float* kk = K + (o * NC + i) * 25;
    float v[25];
    float mn = 1e30f, mx = -1e30f;
    #pragma unroll
    for (int s = 0; s < 25; s++) {
        v[s] = kc[s] * (1.0f / 2048.0f);
        mn = fminf(mn, v[s]); mx = fmaxf(mx, v[s]);
    }
    float inv = 1.0f / (mx - mn + 1e-10f);
    float mn2 = 1e30f, mx2 = -1e30f;
    #pragma unroll
    for (int s = 0; s < 25; s++) {
        v[s] = 0.9f * kk[s] + 0.1f * ((v[s] - mn) * inv);
        mn2 = fminf(mn2, v[s]); mx2 = fmaxf(mx2, v[s]);
    }
    float inv2 = 1.0f / (mx2 - mn2 + 1e-10f);
    float* dst = g_W2 + (o * NC + i) * 25;
    #pragma unroll
    for (int s = 0; s < 25; s++) dst[s] = tf32r((v[s] - mn2) * inv2);
}

// ---------------- kernel 5: L2 conv + output via tf32 mma (smem A, k-permuted) ----------------
#define A_STR 40    // == 8 (mod 32): conflict-free float2 A loads
__global__ __launch_bounds__(128, 2) void k_l2mma(float* __restrict__ out) {
    __shared__ float sA[2][32 * A_STR];          // W2 slice, cols 25..31 zero
    __shared__ __align__(16) float sP[2][480];   // 8 pad rows x 60
    __shared__ int wl[32];
    int q = blockIdx.x, b = blockIdx.y;
    int tid = threadIdx.x, wid = tid >> 5, lane = tid & 31;
    int gid = lane >> 2, tig = lane & 3;
    if (tid < 32) wl[tid] = g_fmidx[b * NFM + tid];
    for (int p = tid; p < 2 * 32 * A_STR; p += 128) ((float*)sA)[p] = 0.f;
    __syncthreads();

    // k-permutation: fragment k=tig -> xy col 2*tig, k=tig+4 -> xy col 2*tig+1
    int offk[4][2];
    #pragma unroll
    for (int ks = 0; ks < 4; ks++) {
        #pragma unroll
        for (int hh = 0; hh < 2; hh++) {
            int xy = ks * 8 + 2 * tig + hh; if (xy > 24) xy = 24;
            int kx = xy / 5, ky = xy - kx * 5;
            offk[ks][hh] = kx * 60 + ky;
        }
    }
    int ntBeg = wid * 7;           // 28 n-tiles, 7 per warp
    float acc[7][2][4];
    #pragma unroll
    for (int j = 0; j < 7; j++)
        #pragma unroll
        for (int m = 0; m < 2; m++)
            #pragma unroll
            for (int v = 0; v < 4; v++) acc[j][m][v] = 0.f;

    {   // preload i = 0
        int iCh = wl[0];
        unsigned dA = (unsigned)__cvta_generic_to_shared(&sA[0][0]);
        for (int idx = tid; idx < 800; idx += 128) {
            int m = idx / 25, k = idx - m * 25;
            cp4(dA + (unsigned)((m * A_STR + k) * 4),
                g_W2 + ((size_t)wl[m] * NC + iCh) * 25 + k);
        }
        unsigned dP = (unsigned)__cvta_generic_to_shared(&sP[0][0]);
        const float* src = &g_Pad[b][0][0] + q * 240;
        for (int idx = tid; idx < 120; idx += 128)
            cp16(dP + (unsigned)(idx * 16), src + idx * 4);
        cp_commit();
    }
    for (int i = 0; i < 32; i++) {
        int st = i & 1;
        if (i + 1 < 32) {
            int iCh = wl[i + 1];
            unsigned dA = (unsigned)__cvta_generic_to_shared(&sA[st ^ 1][0]);
            for (int idx = tid; idx < 800; idx += 128) {
                int m = idx / 25, k = idx - m * 25;
                cp4(dA + (unsigned)((m * A_STR + k) * 4),
                    g_W2 + ((size_t)wl[m] * NC + iCh) * 25 + k);
            }
            unsigned dP = (unsigned)__cvta_generic_to_shared(&sP[st ^ 1][0]);
            const float* src = &g_Pad[b][i + 1][0] + q * 240;
            for (int idx = tid; idx < 120; idx += 128)
                cp16(dP + (unsigned)(idx * 16), src + idx * 4);
            cp_commit();
            asm volatile("cp.async.wait_group 1;" ::: "memory");
        } else {
            asm volatile("cp.async.wait_group 0;" ::: "memory");
        }
        __syncthreads();
        const float* Ax = &sA[st][0];
        const float* Pz = &sP[st][0];
        unsigned aF[2][4][4];
        #pragma unroll
        for (int mt = 0; mt < 2; mt++)
            #pragma unroll
            for (int ks = 0; ks < 4; ks++) {
                int base = (mt * 16 + gid) * A_STR + ks * 8 + 2 * tig;
                float2 v0 = *(const float2*)(Ax + base);              // a0 (k=tig), a2 (k=tig+4)
                float2 v1 = *(const float2*)(Ax + base + 8 * A_STR);  // a1, a3
                aF[mt][ks][0] = __float_as_uint(v0.x);
                aF[mt][ks][1] = __float_as_uint(v1.x);
                aF[mt][ks][2] = __float_as_uint(v0.y);
                aF[mt][ks][3] = __float_as_uint(v1.y);
            }
        #pragma unroll
        for (int j = 0; j < 7; j++) {
            int lp = (ntBeg + j) * 8 + gid;        // 0..223
            int r = (lp * 1171) >> 16;             // lp / 56
            int base = lp + r * 4;                 // r*60 + (lp - r*56)
            #pragma unroll
            for (int ks = 0; ks < 4; ks++) {
                unsigned b0 = __float_as_uint(Pz[base + offk[ks][0]]);
                unsigned b1 = __float_as_uint(Pz[base + offk[ks][1]]);
                mma_tf32(acc[j][0], aF[0][ks][0], aF[0][ks][1], aF[0][ks][2],
                         aF[0][ks][3], b0, b1);
                mma_tf32(acc[j][1], aF[1][ks][0], aF[1][ks][1], aF[1][ks][2],
                         aF[1][ks][3], b0, b1);
            }
        }
        __syncthreads();
    }
    const float cmul = 0.1f / 32.0f;
    #pragma unroll
    for (int j = 0; j < 7; j++) {
        int p = q * 224 + (ntBeg + j) * 8 + tig * 2;
        #pragma unroll
        for (int mt = 0; mt < 2; mt++) {
            int fm0 = mt * 16 + gid, fm1 = fm0 + 8;
            const float* ab0 = g_Ab + ((size_t)b * NC + wl[fm0]) * HW;
            const float* ab1 = g_Ab + ((size_t)b * NC + wl[fm1]) * HW;
            float* o0 = out + ((size_t)b * NFM + fm0) * HW;
            float* o1 = out + ((size_t)b * NFM + fm1) * HW;
            o0[p]     = ab0[p]     + cmul * acc[j][mt][0];
            o0[p + 1] = ab0[p + 1] + cmul * acc[j][mt][1];
            o1[p]     = ab1[p]     + cmul * acc[j][mt][2];
            o1[p + 1] = ab1[p + 1] + cmul * acc[j][mt][3];
        }
    }
}

extern "C" void kernel_launch(void* const* d_in, const int* in_sizes, int n_in,
                              void* d_out, int out_size) {
    const float* A     = (const float*)d_in[0];
    const float* K     = (const float*)d_in[1];
    const float* noise = (const float*)d_in[2];
    float* out = (float*)d_out;

    cudaFuncSetAttribute(k_kchange, cudaFuncAttributeMaxDynamicSharedMemorySize, KC_SMEM);

    k_zero<<<400, 1024>>>();
    k_ab<<<512, 256>>>(A, noise);
    k_pad<<<dim3(16, 32), 256>>>();
    k_kchange<<<dim3(16, 16), 256, KC_SMEM>>>();
    k_combine<<<64, 256>>>(K);
    k_l2mma<<<dim3(14, 16), 128>>>(out);
}

// round 14
// speedup vs baseline: 1.2016x; 1.0525x over previous
#include <cuda_runtime.h>

#define HH 56
#define WW 56
#define HW 3136
#define NB 16
#define NFM 32
#define NC 128

// ---------------- device scratch ----------------
__device__ float g_Ab[NB * NC * HW];
__device__ float g_sum[NB * NC];
__device__ int   g_fmidx[NB * NFM];
__device__ float g_Kch[NC * NC * 25];
__device__ float g_W2[NC * NC * 25];
__device__ float g_Pad[NB][NFM][3600];   // padded (60x60) winner channels, tf32-rounded

// bank-engineered n-column -> xy assignment for k_kchange (stride 72):
// bank(xy) = (8*(4-x) - y) mod 32; groups 0,1 conflict-free, group 3 broadcast.
__device__ const int c_xyt[32] = {
    0, 5, 10, 15, 8, 13, 18, 3,
    1, 6, 11, 16, 9, 14, 19, 4,
    2, 7, 12, 17, 21, 23, 20, 24,
    22, 22, 22, 22, 22, 22, 22, 22};

__device__ __forceinline__ int map2i(int i) { return i < 2 ? 3 - i : (i >= 54 ? 107 - i : i); }
__device__ __forceinline__ int mPad(int i)  { return i < 4 ? 5 - i : (i < 56 ? i - 2 : 109 - i); }

__device__ __forceinline__ float tf32r(float x) {
    float r; asm("cvt.rna.tf32.f32 %0, %1;" : "=f"(r) : "f"(x)); return r;
}
__device__ __forceinline__ void cp4(unsigned dst, const float* src) {
    asm volatile("cp.async.ca.shared.global [%0], [%1], 4;" ::
                 "r"(dst), "l"(__cvta_generic_to_global(src)));
}
__device__ __forceinline__ void cp8(unsigned dst, const float* src) {
    asm volatile("cp.async.ca.shared.global [%0], [%1], 8;" ::
                 "r"(dst), "l"(__cvta_generic_to_global(src)));
}
__device__ __forceinline__ void cp16(unsigned dst, const float* src) {
    asm volatile("cp.async.cg.shared.global [%0], [%1], 16;" ::
                 "r"(dst), "l"(__cvta_generic_to_global(src)));
}
__device__ __forceinline__ void cp_commit() { asm volatile("cp.async.commit_group;"); }

__device__ __forceinline__ void mma_tf32(float* d, unsigned a0, unsigned a1, unsigned a2,
                                         unsigned a3, unsigned b0, unsigned b1) {
    asm volatile("mma.sync.aligned.m16n8k8.row.col.f32.tf32.tf32.f32 "
                 "{%0,%1,%2,%3}, {%4,%5,%6,%7}, {%8,%9}, {%0,%1,%2,%3};"
                 : "+f"(d[0]), "+f"(d[1]), "+f"(d[2]), "+f"(d[3])
                 : "r"(a0), "r"(a1), "r"(a2), "r"(a3), "r"(b0), "r"(b1));
}

// ---------------- kernel 1: Ab + per-map sums ----------------
__global__ __launch_bounds__(256) void k_ab(const float* __restrict__ A,
                                            const float* __restrict__ noise) {
    __shared__ float sA[HW];
    __shared__ float red[8];
    int bf = blockIdx.x;             // b*32 + fm
    int b = bf >> 5, fm = bf & 31;
    const float4* a4 = (const float4*)(A + (size_t)(b * NFM + fm) * HW);
    for (int p = threadIdx.x; p < 784; p += 256) ((float4*)sA)[p] = a4[p];
    __syncthreads();
    for (int r = 0; r < 4; r++) {
        int c = r * NFM + fm;
        const float4* n4 = (const float4*)(noise + ((size_t)b * NC + c) * HW);
        float4* o4 = (float4*)(g_Ab + ((size_t)b * NC + c) * HW);
        float s = 0.0f;
        for (int p = threadIdx.x; p < 784; p += 256) {
            float4 nv = n4[p];
            int pix = p * 4;
            int h = (pix * 37450) >> 21;     // pix / 56
            int w = pix - h * WW;
            int hm = map2i(h) * WW;
            float4 v;
            v.x = fmaxf(sA[hm + map2i(w)]     + 0.1f * nv.x, 0.0f);
            v.y = fmaxf(sA[hm + map2i(w + 1)] + 0.1f * nv.y, 0.0f);
            v.z = fmaxf(sA[hm + map2i(w + 2)] + 0.1f * nv.z, 0.0f);
            v.w = fmaxf(sA[hm + map2i(w + 3)] + 0.1f * nv.w, 0.0f);
            o4[p] = v;
            s += v.x + v.y + v.z + v.w;
        }
        #pragma unroll
        for (int o = 16; o; o >>= 1) s += __shfl_xor_sync(0xffffffffu, s, o);
        if ((threadIdx.x & 31) == 0) red[threadIdx.x >> 5] = s;
        __syncthreads();
        if (threadIdx.x == 0) {
            float t = 0.0f;
            #pragma unroll
            for (int i = 0; i < 8; i++) t += red[i];
            g_sum[b * NC + c] = t;
        }
        __syncthreads();
    }
}

// ---------------- kernel 2: winners + padded winner channels + Kch zeroing (fused) ----------------
__global__ __launch_bounds__(256) void k_pad() {
    int b = blockIdx.x, j = blockIdx.y;
    // zero a slice of g_Kch: 512 blocks x 800 = 409600 floats exactly
    int bz = (b * NFM + j) * 800;
    for (int p = threadIdx.x; p < 800; p += 256) g_Kch[bz + p] = 0.0f;
    const float* s = g_sum + b * NC;
    float best = s[j];
    int wi = 0;
    #pragma unroll
    for (int r = 1; r < 4; r++) {
        float v = s[r * NFM + j];
        if (v > best) { best = v; wi = r; }
    }
    int c = wi * NFM + j;
    if (threadIdx.x == 0) g_fmidx[b * NFM + j] = c;
    const float* src = g_Ab + (size_t)(b * NC + c) * HW;
    float* dst = &g_Pad[b][j][0];
    for (int p = threadIdx.x; p < 3600; p += 256) {
        int r = p / 60, w = p - r * 60;
        dst[p] = tf32r(src[mPad(r) * WW + mPad(w)]);
    }
}

// ---------------- kernel 3: K_change via tf32 mma.sync (bank-engineered B) ----------------
#define AM_STRIDE 232                 // == 8 (mod 32): conflict-free float2 A loads
#define AM_FLTS  (32 * AM_STRIDE)     // 7424
#define AB_RSTR  72                   // row stride == 8 (mod 32): bank-engineered B
#define AB_CSTR  (8 * AB_RSTR)        // 576 per a-channel
#define AB_FLTS  (8 * AB_CSTR)        // 4608
#define KC_SMEM  ((2 * AM_FLTS + 2 * AB_FLTS) * 4)   // 96256 B

__device__ __forceinline__ void kc_load_chunk(float* smA, float* smB, const float* abB,
                                              const int* sWin, int aBase, int cc, int tid) {
    unsigned dA = (unsigned)__cvta_generic_to_shared(smA);
    #pragma unroll
    for (int t = 0; t < 7; t++) {             // 1792 cp16: Am 32j x 4 rows x 14 chunks
        int idx = tid + t * 256;
        int jr = idx / 14;
        int k = idx - jr * 14;
        int j = jr >> 2, r = jr & 3;
        cp16(dA + (unsigned)(j * (AM_STRIDE * 4) + r * 224 + k * 16),
             abB + (size_t)sWin[j] * HW + (cc * 4 + r) * WW + k * 4);
    }
    unsigned dB = (unsigned)__cvta_generic_to_shared(smB);
    #pragma unroll
    for (int t = 0; t < 7; t++) {             // 1792 cp8: Ab 8a x 8 pad rows x 28 chunks
        int idx = tid + t * 256;
        int a = idx / 224;
        int rem = idx - a * 224;
        int rr = rem / 28, w = (rem - rr * 28) * 2;
        int g = cc * 4 + rr;
        unsigned off = (unsigned)((a * AB_CSTR + rr * AB_RSTR + 2 + w) * 4);
        if (g >= 2 && g <= 57) {
            cp8(dB + off, abB + (size_t)(aBase + a) * HW + (g - 2) * WW + w);
        } else {
            *(float2*)(smB + a * AB_CSTR + rr * AB_RSTR + 2 + w) = make_float2(0.f, 0.f);
        }
    }
}

__global__ __launch_bounds__(256, 2) void k_kchange() {
    extern __shared__ __align__(16) float dyn[];
    float* smA = dyn;
    float* smB = dyn + 2 * AM_FLTS;
    __shared__ int sWin[32];
    int atile = blockIdx.x, b = blockIdx.y;
    int tid = threadIdx.x, wid = tid >> 5, lane = tid & 31;
    int gid = lane >> 2, tig = lane & 3;
    if (tid < 32) sWin[tid] = g_fmidx[b * NFM + tid];
    for (int p = tid; p < 2 * AB_FLTS; p += 256) smB[p] = 0.f;   // halos/pads stay zero
    __syncthreads();
    const float* abB = g_Ab + (size_t)(b * NC) * HW;
    int aBase = atile * 8;
    int cbs[4];
    #pragma unroll
    for (int jt = 0; jt < 4; jt++) {
        int xy = c_xyt[jt * 8 + gid];
        int x = xy / 5, y = xy - x * 5;
        cbs[jt] = (4 - x) * AB_RSTR + (4 - y);
    }
    float d[2][4][4];
    #pragma unroll
    for (int m = 0; m < 2; m++)
        #pragma unroll
        for (int jt = 0; jt < 4; jt++)
            #pragma unroll
            for (int q = 0; q < 4; q++) d[m][jt][q] = 0.f;

    kc_load_chunk(smA, smB, abB, sWin, aBase, 0, tid);
    cp_commit();
    // k-permutation: fragment k=tig -> pixel 2*tig, k=tig+4 -> pixel 2*tig+1
    int aOff0 = gid * AM_STRIDE + 2 * tig;
    for (int cc = 0; cc < 14; cc++) {
        int st = cc & 1;
        if (cc + 1 < 14) {
            kc_load_chunk(smA + (st ^ 1) * AM_FLTS, smB + (st ^ 1) * AB_FLTS,
                          abB, sWin, aBase, cc + 1, tid);
            cp_commit();
            asm volatile("cp.async.wait_group 1;" ::: "memory");
        } else {
            asm volatile("cp.async.wait_group 0;" ::: "memory");
        }
        __syncthreads();
        const float* Ax = smA + st * AM_FLTS;
        const float* Bx = smB + st * AB_FLTS + wid * AB_CSTR;
        #pragma unroll
        for (int rl = 0; rl < 4; rl++) {
            #pragma unroll
            for (int ws = 0; ws < 7; ws++) {
                int ao = aOff0 + rl * 56 + ws * 8;
                float2 A0 = *(const float2*)(Ax + ao);                    // rows gid
                float2 A1 = *(const float2*)(Ax + ao + 8 * AM_STRIDE);    // gid+8
                float2 A2 = *(const float2*)(Ax + ao + 16 * AM_STRIDE);
                float2 A3 = *(const float2*)(Ax + ao + 24 * AM_STRIDE);
                int bo = rl * AB_RSTR + ws * 8 + 2 * tig;
                #pragma unroll
                for (int jt = 0; jt < 4; jt++) {
                    unsigned b0 = __float_as_uint(Bx[cbs[jt] + bo]);
                    unsigned b1 = __float_as_uint(Bx[cbs[jt] + bo + 1]);
                    mma_tf32(d[0][jt], __float_as_uint(A0.x), __float_as_uint(A1.x),
                             __float_as_uint(A0.y), __float_as_uint(A1.y), b0, b1);
                    mma_tf32(d[1][jt], __float_as_uint(A2.x), __float_as_uint(A3.x),
                             __float_as_uint(A2.y), __float_as_uint(A3.y), b0, b1);
                }
            }
        }
        __syncthreads();
    }
    int aCh = aBase + wid;
    #pragma unroll
    for (int m = 0; m < 2; m++) {
        int c0 = sWin[m * 16 + gid];
        int c1 = sWin[m * 16 + gid + 8];
        #pragma unroll
        for (int jt = 0; jt < 4; jt++) {
            int xyA = c_xyt[jt * 8 + 2 * tig];
            int xyB = c_xyt[jt * 8 + 2 * tig + 1];
            bool vA = (jt < 3) || (tig == 0);   // group 3: single broadcast column
            bool vB = (jt < 3);
            if (vA) {
                atomicAdd(g_Kch + c0 * 3200 + aCh * 25 + xyA, d[m][jt][0]);
                atomicAdd(g_Kch + c1 * 3200 + aCh * 25 + xyA, d[m][jt][2]);
            }
            if (vB) {
                atomicAdd(g_Kch + c0 * 3200 + aCh * 25 + xyB, d[m][jt][1]);
                atomicAdd(g_Kch + c1 * 3200 + aCh * 25 + xyB, d[m][jt][3]);
            }
        }
    }
}

// ---------------- kernel 4: combine weights (tf32-rounded output) ----------------
__global__ __launch_bounds__(256) void k_combine(const float* __restrict__ K) {
    int t = blockIdx.x * 256 + threadIdx.x;
    int o = t >> 7, i = t & 127;
    const float* kc = g_Kch + (i * NC + o) * 25;
    const float* kk = K + (o * NC + i) * 25;
    float v[25];
    float mn = 1e30f, mx = -1e30f;
    #pragma unroll
    for (int s = 0; s < 25; s++) {
        v[s] = kc[s] * (1.0f / 2048.0f);
        mn = fminf(mn, v[s]); mx = fmaxf(mx, v[s]);
    }
    float inv = 1.0f / (mx - mn + 1e-10f);
    float mn2 = 1e30f, mx2 = -1e30f;
    #pragma unroll
    for (int s = 0; s < 25; s++) {
        v[s] = 0.9f * kk[s] + 0.1f * ((v[s] - mn) * inv);
        mn2 = fminf(mn2, v[s]); mx2 = fmaxf(mx2, v[s]);
    }
    float inv2 = 1.0f / (mx2 - mn2 + 1e-10f);
    float* dst = g_W2 + (o * NC + i) * 25;
    #pragma unroll
    for (int s = 0; s < 25; s++) dst[s] = tf32r((v[s] - mn2) * inv2);
}

// ---------------- kernel 5: L2 conv + output via tf32 mma (smem A, k-permuted) ----------------
#define A_STR 40    // == 8 (mod 32): conflict-free float2 A loads
__global__ __launch_bounds__(128, 2) void k_l2mma(float* __restrict__ out) {
    __shared__ float sA[2][32 * A_STR];          // W2 slice, cols 25..31 zero
    __shared__ __align__(16) float sP[2][480];   // 8 pad rows x 60
    __shared__ int wl[32];
    int q = blockIdx.x, b = blockIdx.y;
    int tid = threadIdx.x, wid = tid >> 5, lane = tid & 31;
    int gid = lane >> 2, tig = lane & 3;
    if (tid < 32) wl[tid] = g_fmidx[b * NFM + tid];
    for (int p = tid; p < 2 * 32 * A_STR; p += 128) ((float*)sA)[p] = 0.f;
    __syncthreads();

    int offk[4][2];
    #pragma unroll
    for (int ks = 0; ks < 4; ks++) {
        #pragma unroll
        for (int hh = 0; hh < 2; hh++) {
            int xy = ks * 8 + 2 * tig + hh; if (xy > 24) xy = 24;
            int kx = xy / 5, ky = xy - kx * 5;
            offk[ks][hh] = kx * 60 + ky;
        }
    }
    int ntBeg = wid * 7;
    float acc[7][2][4];
    #pragma unroll
    for (int j = 0; j < 7; j++)
        #pragma unroll
        for (int m = 0; m < 2; m++)
            #pragma unroll
            for (int v = 0; v < 4; v++) acc[j][m][v] = 0.f;

    {   // preload i = 0
        int iCh = wl[0];
        unsigned dA = (unsigned)__cvta_generic_to_shared(&sA[0][0]);
        for (int idx = tid; idx < 800; idx += 128) {
            int m = idx / 25, k = idx - m * 25;
            cp4(dA + (unsigned)((m * A_STR + k) * 4),
                g_W2 + ((size_t)wl[m] * NC + iCh) * 25 + k);
        }
        unsigned dP = (unsigned)__cvta_generic_to_shared(&sP[0][0]);
        const float* src = &g_Pad[b][0][0] + q * 240;
        for (int idx = tid; idx < 120; idx += 128)
            cp16(dP + (unsigned)(idx * 16), src + idx * 4);
        cp_commit();
    }
    for (int i = 0; i < 32; i++) {
        int st = i & 1;
        if (i + 1 < 32) {
            int iCh = wl[i + 1];
            unsigned dA = (unsigned)__cvta_generic_to_shared(&sA[st ^ 1][0]);
            for (int idx = tid; idx < 800; idx += 128) {
                int m = idx / 25, k = idx - m * 25;
                cp4(dA + (unsigned)((m * A_STR + k) * 4),
                    g_W2 + ((size_t)wl[m] * NC + iCh) * 25 + k);
            }
            unsigned dP = (unsigned)__cvta_generic_to_shared(&sP[st ^ 1][0]);
            const float* src = &g_Pad[b][i + 1][0] + q * 240;
            for (int idx = tid; idx < 120; idx += 128)
                cp16(dP + (unsigned)(idx * 16), src + idx * 4);
            cp_commit();
            asm volatile("cp.async.wait_group 1;" ::: "memory");
        } else {
            asm volatile("cp.async.wait_group 0;" ::: "memory");
        }
        __syncthreads();
        const float* Ax = &sA[st][0];
        const float* Pz = &sP[st][0];
        unsigned aF[2][4][4];
        #pragma unroll
        for (int mt = 0; mt < 2; mt++)
            #pragma unroll
            for (int ks = 0; ks < 4; ks++) {
                int base = (mt * 16 + gid) * A_STR + ks * 8 + 2 * tig;
                float2 v0 = *(const float2*)(Ax + base);
                float2 v1 = *(const float2*)(Ax + base + 8 * A_STR);
                aF[mt][ks][0] = __float_as_uint(v0.x);
                aF[mt][ks][1] = __float_as_uint(v1.x);
                aF[mt][ks][2] = __float_as_uint(v0.y);
                aF[mt][ks][3] = __float_as_uint(v1.y);
            }
        #pragma unroll
        for (int j = 0; j < 7; j++) {
            int lp = (ntBeg + j) * 8 + gid;
            int r = (lp * 1171) >> 16;
            int base = lp + r * 4;
            #pragma unroll
            for (int ks = 0; ks < 4; ks++) {
                unsigned b0 = __float_as_uint(Pz[base + offk[ks][0]]);
                unsigned b1 = __float_as_uint(Pz[base + offk[ks][1]]);
                mma_tf32(acc[j][0], aF[0][ks][0], aF[0][ks][1], aF[0][ks][2],
                         aF[0][ks][3], b0, b1);
                mma_tf32(acc[j][1], aF[1][ks][0], aF[1][ks][1], aF[1][ks][2],
                         aF[1][ks][3], b0, b1);
            }
        }
        __syncthreads();
    }
    const float cmul = 0.1f / 32.0f;
    #pragma unroll
    for (int j = 0; j < 7; j++) {
        int p = q * 224 + (ntBeg + j) * 8 + tig * 2;
        #pragma unroll
        for (int mt = 0; mt < 2; mt++) {
            int fm0 = mt * 16 + gid, fm1 = fm0 + 8;
            const float* ab0 = g_Ab + ((size_t)b * NC + wl[fm0]) * HW;
            const float* ab1 = g_Ab + ((size_t)b * NC + wl[fm1]) * HW;
            float* o0 = out + ((size_t)b * NFM + fm0) * HW;
            float* o1 = out + ((size_t)b * NFM + fm1) * HW;
            o0[p]     = ab0[p]     + cmul * acc[j][mt][0];
            o0[p + 1] = ab0[p + 1] + cmul * acc[j][mt][1];
            o1[p]     = ab1[p]     + cmul * acc[j][mt][2];
            o1[p + 1] = ab1[p + 1] + cmul * acc[j][mt][3];
        }
    }
}

extern "C" void kernel_launch(void* const* d_in, const int* in_sizes, int n_in,
                              void* d_out, int out_size) {
    const float* A     = (const float*)d_in[0];
    const float* K     = (const float*)d_in[1];
    const float* noise = (const float*)d_in[2];
    float* out = (float*)d_out;

    cudaFuncSetAttribute(k_kchange, cudaFuncAttributeMaxDynamicSharedMemorySize, KC_SMEM);

    k_ab<<<512, 256>>>(A, noise);
    k_pad<<<dim3(16, 32), 256>>>();
    k_kchange<<<dim3(16, 16), 256, KC_SMEM>>>();
    k_combine<<<64, 256>>>(K);
    k_l2mma<<<dim3(14, 16), 128>>>(out);
}

// round 15
// speedup vs baseline: 1.3167x; 1.0958x over previous
#include <cuda_runtime.h>

#define HH 56
#define WW 56
#define HW 3136
#define NB 16
#define NFM 32
#define NC 128

// ---------------- device scratch ----------------
__device__ float g_Ab[NB * NC * HW];
__device__ float g_sum[NB * NC];
__device__ int   g_fmidx[NB * NFM];
__device__ float g_Kch[NC * NC * 25];
__device__ float g_W2[NC * NC * 25];
__device__ float g_W2g[NB * NFM * NFM * 28];  // gathered W2[wl[fm],wl[ii],:25] pad to 28
__device__ float g_Pad[NB][NFM][3600];        // padded (60x60) winner channels, tf32-rounded

// bank-engineered n-column -> xy assignment for k_kchange (stride 72):
__device__ const int c_xyt[32] = {
    0, 5, 10, 15, 8, 13, 18, 3,
    1, 6, 11, 16, 9, 14, 19, 4,
    2, 7, 12, 17, 21, 23, 20, 24,
    22, 22, 22, 22, 22, 22, 22, 22};

__device__ __forceinline__ int map2i(int i) { return i < 2 ? 3 - i : (i >= 54 ? 107 - i : i); }
__device__ __forceinline__ int mPad(int i)  { return i < 4 ? 5 - i : (i < 56 ? i - 2 : 109 - i); }

__device__ __forceinline__ float tf32r(float x) {
    float r; asm("cvt.rna.tf32.f32 %0, %1;" : "=f"(r) : "f"(x)); return r;
}
__device__ __forceinline__ void cp8(unsigned dst, const float* src) {
    asm volatile("cp.async.ca.shared.global [%0], [%1], 8;" ::
                 "r"(dst), "l"(__cvta_generic_to_global(src)));
}
__device__ __forceinline__ void cp16(unsigned dst, const float* src) {
    asm volatile("cp.async.cg.shared.global [%0], [%1], 16;" ::
                 "r"(dst), "l"(__cvta_generic_to_global(src)));
}
__device__ __forceinline__ void cp_commit() { asm volatile("cp.async.commit_group;"); }

__device__ __forceinline__ void mma_tf32(float* d, unsigned a0, unsigned a1, unsigned a2,
                                         unsigned a3, unsigned b0, unsigned b1) {
    asm volatile("mma.sync.aligned.m16n8k8.row.col.f32.tf32.tf32.f32 "
                 "{%0,%1,%2,%3}, {%4,%5,%6,%7}, {%8,%9}, {%0,%1,%2,%3};"
                 : "+f"(d[0]), "+f"(d[1]), "+f"(d[2]), "+f"(d[3])
                 : "r"(a0), "r"(a1), "r"(a2), "r"(a3), "r"(b0), "r"(b1));
}

// ---------------- kernel 1: Ab + per-map sums (2 replicas per block) ----------------
__global__ __launch_bounds__(256) void k_ab(const float* __restrict__ A,
                                            const float* __restrict__ noise) {
    __shared__ float sA[HW];
    __shared__ float red[8];
    int bf = blockIdx.x >> 1, half = blockIdx.x & 1;
    int b = bf >> 5, fm = bf & 31;
    const float4* a4 = (const float4*)(A + (size_t)(b * NFM + fm) * HW);
    for (int p = threadIdx.x; p < 784; p += 256) ((float4*)sA)[p] = a4[p];
    __syncthreads();
    for (int r = half * 2; r < half * 2 + 2; r++) {
        int c = r * NFM + fm;
        const float4* n4 = (const float4*)(noise + ((size_t)b * NC + c) * HW);
        float4* o4 = (float4*)(g_Ab + ((size_t)b * NC + c) * HW);
        float s = 0.0f;
        for (int p = threadIdx.x; p < 784; p += 256) {
            float4 nv = n4[p];
            int pix = p * 4;
            int h = (pix * 37450) >> 21;     // pix / 56
            int w = pix - h * WW;
            int hm = map2i(h) * WW;
            float4 v;
            v.x = fmaxf(sA[hm + map2i(w)]     + 0.1f * nv.x, 0.0f);
            v.y = fmaxf(sA[hm + map2i(w + 1)] + 0.1f * nv.y, 0.0f);
            v.z = fmaxf(sA[hm + map2i(w + 2)] + 0.1f * nv.z, 0.0f);
            v.w = fmaxf(sA[hm + map2i(w + 3)] + 0.1f * nv.w, 0.0f);
            o4[p] = v;
            s += v.x + v.y + v.z + v.w;
        }
        #pragma unroll
        for (int o = 16; o; o >>= 1) s += __shfl_xor_sync(0xffffffffu, s, o);
        if ((threadIdx.x & 31) == 0) red[threadIdx.x >> 5] = s;
        __syncthreads();
        if (threadIdx.x == 0) {
            float t = 0.0f;
            #pragma unroll
            for (int i = 0; i < 8; i++) t += red[i];
            g_sum[b * NC + c] = t;
        }
        __syncthreads();
    }
}

// ---------------- kernel 2: winners + padded winner channels + Kch zeroing (fused) ----------------
__global__ __launch_bounds__(256) void k_pad() {
    int b = blockIdx.x, j = blockIdx.y;
    int bz = (b * NFM + j) * 800;        // 512 x 800 = 409600 exactly
    for (int p = threadIdx.x; p < 800; p += 256) g_Kch[bz + p] = 0.0f;
    const float* s = g_sum + b * NC;
    float best = s[j];
    int wi = 0;
    #pragma unroll
    for (int r = 1; r < 4; r++) {
        float v = s[r * NFM + j];
        if (v > best) { best = v; wi = r; }
    }
    int c = wi * NFM + j;
    if (threadIdx.x == 0) g_fmidx[b * NFM + j] = c;
    const float* src = g_Ab + (size_t)(b * NC + c) * HW;
    float* dst = &g_Pad[b][j][0];
    for (int p = threadIdx.x; p < 3600; p += 256) {
        int r = p / 60, w = p - r * 60;
        dst[p] = tf32r(src[mPad(r) * WW + mPad(w)]);
    }
}

// ---------------- kernel 3: K_change via tf32 mma.sync (bank-engineered B) ----------------
#define AM_STRIDE 232
#define AM_FLTS  (32 * AM_STRIDE)
#define AB_RSTR  72
#define AB_CSTR  (8 * AB_RSTR)
#define AB_FLTS  (8 * AB_CSTR)
#define KC_SMEM  ((2 * AM_FLTS + 2 * AB_FLTS) * 4)

__device__ __forceinline__ void kc_load_chunk(float* smA, float* smB, const float* abB,
                                              const int* sWin, int aBase, int cc, int tid) {
    unsigned dA = (unsigned)__cvta_generic_to_shared(smA);
    #pragma unroll
    for (int t = 0; t < 7; t++) {
        int idx = tid + t * 256;
        int jr = idx / 14;
        int k = idx - jr * 14;
        int j = jr >> 2, r = jr & 3;
        cp16(dA + (unsigned)(j * (AM_STRIDE * 4) + r * 224 + k * 16),
             abB + (size_t)sWin[j] * HW + (cc * 4 + r) * WW + k * 4);
    }
    unsigned dB = (unsigned)__cvta_generic_to_shared(smB);
    #pragma unroll
    for (int t = 0; t < 7; t++) {
        int idx = tid + t * 256;
        int a = idx / 224;
        int rem = idx - a * 224;
        int rr = rem / 28, w = (rem - rr * 28) * 2;
        int g = cc * 4 + rr;
        unsigned off = (unsigned)((a * AB_CSTR + rr * AB_RSTR + 2 + w) * 4);
        if (g >= 2 && g <= 57) {
            cp8(dB + off, abB + (size_t)(aBase + a) * HW + (g - 2) * WW + w);
        } else {
            *(float2*)(smB + a * AB_CSTR + rr * AB_RSTR + 2 + w) = make_float2(0.f, 0.f);
        }
    }
}

__global__ __launch_bounds__(256, 2) void k_kchange() {
    extern __shared__ __align__(16) float dyn[];
    float* smA = dyn;
    float* smB = dyn + 2 * AM_FLTS;
    __shared__ int sWin[32];
    int atile = blockIdx.x, b = blockIdx.y;
    int tid = threadIdx.x, wid = tid >> 5, lane = tid & 31;
    int gid = lane >> 2, tig = lane & 3;
    if (tid < 32) sWin[tid] = g_fmidx[b * NFM + tid];
    for (int p = tid; p < 2 * AB_FLTS; p += 256) smB[p] = 0.f;
    __syncthreads();
    const float* abB = g_Ab + (size_t)(b * NC) * HW;
    int aBase = atile * 8;
    int cbs[4];
    #pragma unroll
    for (int jt = 0; jt < 4; jt++) {
        int xy = c_xyt[jt * 8 + gid];
        int x = xy / 5, y = xy - x * 5;
        cbs[jt] = (4 - x) * AB_RSTR + (4 - y);
    }
    float d[2][4][4];
    #pragma unroll
    for (int m = 0; m < 2; m++)
        #pragma unroll
        for (int jt = 0; jt < 4; jt++)
            #pragma unroll
            for (int q = 0; q < 4; q++) d[m][jt][q] = 0.f;

    kc_load_chunk(smA, smB, abB, sWin, aBase, 0, tid);
    cp_commit();
    int aOff0 = gid * AM_STRIDE + 2 * tig;
    for (int cc = 0; cc < 14; cc++) {
        int st = cc & 1;
        if (cc + 1 < 14) {
            kc_load_chunk(smA + (st ^ 1) * AM_FLTS, smB + (st ^ 1) * AB_FLTS,
                          abB, sWin, aBase, cc + 1, tid);
            cp_commit();
            asm volatile("cp.async.wait_group 1;" ::: "memory");
        } else {
            asm volatile("cp.async.wait_group 0;" ::: "memory");
        }
        __syncthreads();
        const float* Ax = smA + st * AM_FLTS;
        const float* Bx = smB + st * AB_FLTS + wid * AB_CSTR;
        #pragma unroll
        for (int rl = 0; rl < 4; rl++) {
            #pragma unroll
            for (int ws = 0; ws < 7; ws++) {
                int ao = aOff0 + rl * 56 + ws * 8;
                float2 A0 = *(const float2*)(Ax + ao);
                float2 A1 = *(const float2*)(Ax + ao + 8 * AM_STRIDE);
                float2 A2 = *(const float2*)(Ax + ao + 16 * AM_STRIDE);
                float2 A3 = *(const float2*)(Ax + ao + 24 * AM_STRIDE);
                int bo = rl * AB_RSTR + ws * 8 + 2 * tig;
                #pragma unroll
                for (int jt = 0; jt < 4; jt++) {
                    unsigned b0 = __float_as_uint(Bx[cbs[jt] + bo]);
                    unsigned b1 = __float_as_uint(Bx[cbs[jt] + bo + 1]);
                    mma_tf32(d[0][jt], __float_as_uint(A0.x), __float_as_uint(A1.x),
                             __float_as_uint(A0.y), __float_as_uint(A1.y), b0, b1);
                    mma_tf32(d[1][jt], __float_as_uint(A2.x), __float_as_uint(A3.x),
                             __float_as_uint(A2.y), __float_as_uint(A3.y), b0, b1);
                }
            }
        }
        __syncthreads();
    }
    int aCh = aBase + wid;
    #pragma unroll
    for (int m = 0; m < 2; m++) {
        int c0 = sWin[m * 16 + gid];
        int c1 = sWin[m * 16 + gid + 8];
        #pragma unroll
        for (int jt = 0; jt < 4; jt++) {
            int xyA = c_xyt[jt * 8 + 2 * tig];
            int xyB = c_xyt[jt * 8 + 2 * tig + 1];
            bool vA = (jt < 3) || (tig == 0);
            bool vB = (jt < 3);
            if (vA) {
                atomicAdd(g_Kch + c0 * 3200 + aCh * 25 + xyA, d[m][jt][0]);
                atomicAdd(g_Kch + c1 * 3200 + aCh * 25 + xyA, d[m][jt][2]);
            }
            if (vB) {
                atomicAdd(g_Kch + c0 * 3200 + aCh * 25 + xyB, d[m][jt][1]);
                atomicAdd(g_Kch + c1 * 3200 + aCh * 25 + xyB, d[m][jt][3]);
            }
        }
    }
}

// ---------------- kernel 4: combine weights (warp per pair) ----------------
__global__ __launch_bounds__(256) void k_combine(const float* __restrict__ K) {
    int warp = (blockIdx.x * 256 + threadIdx.x) >> 5;   // 0..4095
    int lane = threadIdx.x & 31;
    bool act = lane < 25;
    #pragma unroll
    for (int pp = 0; pp < 4; pp++) {
        int pair = warp * 4 + pp;                        // 0..16383
        int o = pair >> 7, i = pair & 127;
        const float* kc = g_Kch + (i * NC + o) * 25;
        const float* kk = K + (o * NC + i) * 25;
        float v = act ? kc[lane] * (1.0f / 2048.0f) : 0.f;
        float mn = act ? v : 1e30f, mx = act ? v : -1e30f;
        #pragma unroll
        for (int ofs = 16; ofs; ofs >>= 1) {
            mn = fminf(mn, __shfl_xor_sync(0xffffffffu, mn, ofs));
            mx = fmaxf(mx, __shfl_xor_sync(0xffffffffu, mx, ofs));
        }
        float inv = 1.0f / (mx - mn + 1e-10f);
        float w = act ? 0.9f * kk[lane] + 0.1f * ((v - mn) * inv) : 0.f;
        float mn2 = act ? w : 1e30f, mx2 = act ? w : -1e30f;
        #pragma unroll
        for (int ofs = 16; ofs; ofs >>= 1) {
            mn2 = fminf(mn2, __shfl_xor_sync(0xffffffffu, mn2, ofs));
            mx2 = fmaxf(mx2, __shfl_xor_sync(0xffffffffu, mx2, ofs));
        }
        float inv2 = 1.0f / (mx2 - mn2 + 1e-10f);
        if (act) g_W2[(o * NC + i) * 25 + lane] = tf32r((w - mn2) * inv2);
    }
}

// ---------------- kernel 4b: gather W2 winner submatrix, padded to 28 cols ----------------
__global__ __launch_bounds__(256) void k_gather() {
    __shared__ int wl[32];
    int b = blockIdx.x, fm = blockIdx.y;
    if (threadIdx.x < 32) wl[threadIdx.x] = g_fmidx[b * NFM + threadIdx.x];
    __syncthreads();
    int o = wl[fm];
    float* dst = g_W2g + ((size_t)(b * NFM + fm) * NFM) * 28;
    for (int idx = threadIdx.x; idx < 32 * 28; idx += 256) {
        int ii = idx / 28, k = idx - ii * 28;
        dst[idx] = (k < 25) ? g_W2[((size_t)o * NC + wl[ii]) * 25 + k] : 0.f;
    }
}

// ---------------- kernel 5: L2 conv + output via tf32 mma (dense gathered A) ----------------
#define A_STR 40    // == 8 (mod 32): conflict-free float2 A loads; cols 28..39 stay zero
__global__ __launch_bounds__(128, 2) void k_l2mma(float* __restrict__ out) {
    __shared__ float sA[2][32 * A_STR];
    __shared__ __align__(16) float sP[2][480];   // 8 pad rows x 60
    __shared__ int wl[32];
    int q = blockIdx.x, b = blockIdx.y;
    int tid = threadIdx.x, wid = tid >> 5, lane = tid & 31;
    int gid = lane >> 2, tig = lane & 3;
    if (tid < 32) wl[tid] = g_fmidx[b * NFM + tid];
    for (int p = tid; p < 2 * 32 * A_STR; p += 128) ((float*)sA)[p] = 0.f;
    __syncthreads();

    const float* w2g = g_W2g + (size_t)b * NFM * NFM * 28;
    int offk[4][2];
    #pragma unroll
    for (int ks = 0; ks < 4; ks++) {
        #pragma unroll
        for (int hh = 0; hh < 2; hh++) {
            int xy = ks * 8 + 2 * tig + hh; if (xy > 24) xy = 24;
            int kx = xy / 5, ky = xy - kx * 5;
            offk[ks][hh] = kx * 60 + ky;
        }
    }
    int ntBeg = wid * 7;
    float acc[7][2][4];
    #pragma unroll
    for (int j = 0; j < 7; j++)
        #pragma unroll
        for (int m = 0; m < 2; m++)
            #pragma unroll
            for (int v = 0; v < 4; v++) acc[j][m][v] = 0.f;

    {   // preload i = 0: A = 32 rows x 7 cp16, B strip = 120 cp16
        unsigned dA = (unsigned)__cvta_generic_to_shared(&sA[0][0]);
        for (int idx = tid; idx < 224; idx += 128) {
            int m = idx / 7, k7 = idx - m * 7;
            cp16(dA + (unsigned)(m * (A_STR * 4) + k7 * 16),
                 w2g + (size_t)(m * NFM + 0) * 28 + k7 * 4);
        }
        unsigned dP = (unsigned)__cvta_generic_to_shared(&sP[0][0]);
        const float* src = &g_Pad[b][0][0] + q * 240;
        for (int idx = tid; idx < 120; idx += 128)
            cp16(dP + (unsigned)(idx * 16), src + idx * 4);
        cp_commit();
    }
    for (int i = 0; i < 32; i++) {
        int st = i & 1;
        if (i + 1 < 32) {
            unsigned dA = (unsigned)__cvta_generic_to_shared(&sA[st ^ 1][0]);
            for (int idx = tid; idx < 224; idx += 128) {
                int m = idx / 7, k7 = idx - m * 7;
                cp16(dA + (unsigned)(m * (A_STR * 4) + k7 * 16),
                     w2g + (size_t)(m * NFM + i + 1) * 28 + k7 * 4);
            }
            unsigned dP = (unsigned)__cvta_generic_to_shared(&sP[st ^ 1][0]);
            const float* src = &g_Pad[b][i + 1][0] + q * 240;
            for (int idx = tid; idx < 120; idx += 128)
                cp16(dP + (unsigned)(idx * 16), src + idx * 4);
            cp_commit();
            asm volatile("cp.async.wait_group 1;" ::: "memory");
        } else {
            asm volatile("cp.async.wait_group 0;" ::: "memory");
        }
        __syncthreads();
        const float* Ax = &sA[st][0];
        const float* Pz = &sP[st][0];
        unsigned aF[2][4][4];
        #pragma unroll
        for (int mt = 0; mt < 2; mt++)
            #pragma unroll
            for (int ks = 0; ks < 4; ks++) {
                int base = (mt * 16 + gid) * A_STR + ks * 8 + 2 * tig;
                float2 v0 = *(const float2*)(Ax + base);
                float2 v1 = *(const float2*)(Ax + base + 8 * A_STR);
                aF[mt][ks][0] = __float_as_uint(v0.x);
                aF[mt][ks][1] = __float_as_uint(v1.x);
                aF[mt][ks][2] = __float_as_uint(v0.y);
                aF[mt][ks][3] = __float_as_uint(v1.y);
            }
        #pragma unroll
        for (int j = 0; j < 7; j++) {
            int lp = (ntBeg + j) * 8 + gid;
            int r = (lp * 1171) >> 16;
            int base = lp + r * 4;
            #pragma unroll
            for (int ks = 0; ks < 4; ks++) {
                unsigned b0 = __float_as_uint(Pz[base + offk[ks][0]]);
                unsigned b1 = __float_as_uint(Pz[base + offk[ks][1]]);
                mma_tf32(acc[j][0], aF[0][ks][0], aF[0][ks][1], aF[0][ks][2],
                         aF[0][ks][3], b0, b1);
                mma_tf32(acc[j][1], aF[1][ks][0], aF[1][ks][1], aF[1][ks][2],
                         aF[1][ks][3], b0, b1);
            }
        }
        __syncthreads();
    }
    const float cmul = 0.1f / 32.0f;
    #pragma unroll
    for (int j = 0; j < 7; j++) {
        int p = q * 224 + (ntBeg + j) * 8 + tig * 2;
        #pragma unroll
        for (int mt = 0; mt < 2; mt++) {
            int fm0 = mt * 16 + gid, fm1 = fm0 + 8;
            const float* ab0 = g_Ab + ((size_t)b * NC + wl[fm0]) * HW;
            const float* ab1 = g_Ab + ((size_t)b * NC + wl[fm1]) * HW;
            float* o0 = out + ((size_t)b * NFM + fm0) * HW;
            float* o1 = out + ((size_t)b * NFM + fm1) * HW;
            o0[p]     = ab0[p]     + cmul * acc[j][mt][0];
            o0[p + 1] = ab0[p + 1] + cmul * acc[j][mt][1];
            o1[p]     = ab1[p]     + cmul * acc[j][mt][2];
            o1[p + 1] = ab1[p + 1] + cmul * acc[j][mt][3];
        }
    }
}

extern "C" void kernel_launch(void* const* d_in, const int* in_sizes, int n_in,
                              void* d_out, int out_size) {
    const float* A     = (const float*)d_in[0];
    const float* K     = (const float*)d_in[1];
    const float* noise = (const float*)d_in[2];
    float* out = (float*)d_out;

    cudaFuncSetAttribute(k_kchange, cudaFuncAttributeMaxDynamicSharedMemorySize, KC_SMEM);

    k_ab<<<1024, 256>>>(A, noise);
    k_pad<<<dim3(16, 32), 256>>>();
    k_kchange<<<dim3(16, 16), 256, KC_SMEM>>>();
    k_combine<<<512, 256>>>(K);
    k_gather<<<dim3(16, 32), 256>>>();
    k_l2mma<<<dim3(14, 16), 128>>>(out);
}

// round 16
// speedup vs baseline: 1.3900x; 1.0556x over previous
#include <cuda_runtime.h>

#define HH 56
#define WW 56
#define HW 3136
#define NB 16
#define NFM 32
#define NC 128

// ---------------- device scratch ----------------
__device__ float g_Ab[NB * NC * HW];
__device__ float g_sum[NB * NC];
__device__ int   g_fmidx[NB * NFM];
__device__ float g_Kch[NC * NC * 25];
__device__ float g_W2g[NB * NFM * NFM * 28];  // fused combine+gather output, pad to 28
__device__ float g_Pad[NB][NFM][3600];        // padded (60x60) winner channels, tf32-rounded

// bank-engineered n-column -> xy assignment for k_kchange (stride 72):
__device__ const int c_xyt[32] = {
    0, 5, 10, 15, 8, 13, 18, 3,
    1, 6, 11, 16, 9, 14, 19, 4,
    2, 7, 12, 17, 21, 23, 20, 24,
    22, 22, 22, 22, 22, 22, 22, 22};

__device__ __forceinline__ int map2i(int i) { return i < 2 ? 3 - i : (i >= 54 ? 107 - i : i); }
__device__ __forceinline__ int mPad(int i)  { return i < 4 ? 5 - i : (i < 56 ? i - 2 : 109 - i); }

__device__ __forceinline__ float tf32r(float x) {
    float r; asm("cvt.rna.tf32.f32 %0, %1;" : "=f"(r) : "f"(x)); return r;
}
__device__ __forceinline__ void cp8(unsigned dst, const float* src) {
    asm volatile("cp.async.ca.shared.global [%0], [%1], 8;" ::
                 "r"(dst), "l"(__cvta_generic_to_global(src)));
}
__device__ __forceinline__ void cp16(unsigned dst, const float* src) {
    asm volatile("cp.async.cg.shared.global [%0], [%1], 16;" ::
                 "r"(dst), "l"(__cvta_generic_to_global(src)));
}
__device__ __forceinline__ void cp_commit() { asm volatile("cp.async.commit_group;"); }

__device__ __forceinline__ void mma_tf32(float* d, unsigned a0, unsigned a1, unsigned a2,
                                         unsigned a3, unsigned b0, unsigned b1) {
    asm volatile("mma.sync.aligned.m16n8k8.row.col.f32.tf32.tf32.f32 "
                 "{%0,%1,%2,%3}, {%4,%5,%6,%7}, {%8,%9}, {%0,%1,%2,%3};"
                 : "+f"(d[0]), "+f"(d[1]), "+f"(d[2]), "+f"(d[3])
                 : "r"(a0), "r"(a1), "r"(a2), "r"(a3), "r"(b0), "r"(b1));
}

// ---------------- kernel 1: Ab + per-map sums (2 replicas per block) ----------------
__global__ __launch_bounds__(256) void k_ab(const float* __restrict__ A,
                                            const float* __restrict__ noise) {
    __shared__ float sA[HW];
    __shared__ float red[8];
    int bf = blockIdx.x >> 1, half = blockIdx.x & 1;
    int b = bf >> 5, fm = bf & 31;
    const float4* a4 = (const float4*)(A + (size_t)(b * NFM + fm) * HW);
    for (int p = threadIdx.x; p < 784; p += 256) ((float4*)sA)[p] = a4[p];
    __syncthreads();
    for (int r = half * 2; r < half * 2 + 2; r++) {
        int c = r * NFM + fm;
        const float4* n4 = (const float4*)(noise + ((size_t)b * NC + c) * HW);
        float4* o4 = (float4*)(g_Ab + ((size_t)b * NC + c) * HW);
        float s = 0.0f;
        for (int p = threadIdx.x; p < 784; p += 256) {
            float4 nv = n4[p];
            int pix = p * 4;
            int h = (pix * 37450) >> 21;     // pix / 56
            int w = pix - h * WW;
            int hm = map2i(h) * WW;
            float4 v;
            v.x = fmaxf(sA[hm + map2i(w)]     + 0.1f * nv.x, 0.0f);
            v.y = fmaxf(sA[hm + map2i(w + 1)] + 0.1f * nv.y, 0.0f);
            v.z = fmaxf(sA[hm + map2i(w + 2)] + 0.1f * nv.z, 0.0f);
            v.w = fmaxf(sA[hm + map2i(w + 3)] + 0.1f * nv.w, 0.0f);
            o4[p] = v;
            s += v.x + v.y + v.z + v.w;
        }
        #pragma unroll
        for (int o = 16; o; o >>= 1) s += __shfl_xor_sync(0xffffffffu, s, o);
        if ((threadIdx.x & 31) == 0) red[threadIdx.x >> 5] = s;
        __syncthreads();
        if (threadIdx.x == 0) {
            float t = 0.0f;
            #pragma unroll
            for (int i = 0; i < 8; i++) t += red[i];
            g_sum[b * NC + c] = t;
        }
        __syncthreads();
    }
}

// ---------------- kernel 2: winners + padded winner channels + Kch zeroing (fused) ----------------
__global__ __launch_bounds__(256) void k_pad() {
    int b = blockIdx.x, j = blockIdx.y;
    int bz = (b * NFM + j) * 800;        // 512 x 800 = 409600 exactly
    for (int p = threadIdx.x; p < 800; p += 256) g_Kch[bz + p] = 0.0f;
    const float* s = g_sum + b * NC;
    float best = s[j];
    int wi = 0;
    #pragma unroll
    for (int r = 1; r < 4; r++) {
        float v = s[r * NFM + j];
        if (v > best) { best = v; wi = r; }
    }
    int c = wi * NFM + j;
    if (threadIdx.x == 0) g_fmidx[b * NFM + j] = c;
    const float* src = g_Ab + (size_t)(b * NC + c) * HW;
    float* dst = &g_Pad[b][j][0];
    for (int p = threadIdx.x; p < 3600; p += 256) {
        int r = p / 60, w = p - r * 60;
        dst[p] = tf32r(src[mPad(r) * WW + mPad(w)]);
    }
}

// ---------------- kernel 3: K_change via tf32 mma.sync (bank-engineered B) ----------------
#define AM_STRIDE 232
#define AM_FLTS  (32 * AM_STRIDE)
#define AB_RSTR  72
#define AB_CSTR  (8 * AB_RSTR)
#define AB_FLTS  (8 * AB_CSTR)
#define KC_SMEM  ((2 * AM_FLTS + 2 * AB_FLTS) * 4)

__device__ __forceinline__ void kc_load_chunk(float* smA, float* smB, const float* abB,
                                              const int* sWin, int aBase, int cc, int tid) {
    unsigned dA = (unsigned)__cvta_generic_to_shared(smA);
    #pragma unroll
    for (int t = 0; t < 7; t++) {
        int idx = tid + t * 256;
        int jr = idx / 14;
        int k = idx - jr * 14;
        int j = jr >> 2, r = jr & 3;
        cp16(dA + (unsigned)(j * (AM_STRIDE * 4) + r * 224 + k * 16),
             abB + (size_t)sWin[j] * HW + (cc * 4 + r) * WW + k * 4);
    }
    unsigned dB = (unsigned)__cvta_generic_to_shared(smB);
    #pragma unroll
    for (int t = 0; t < 7; t++) {
        int idx = tid + t * 256;
        int a = idx / 224;
        int rem = idx - a * 224;
        int rr = rem / 28, w = (rem - rr * 28) * 2;
        int g = cc * 4 + rr;
        unsigned off = (unsigned)((a * AB_CSTR + rr * AB_RSTR + 2 + w) * 4);
        if (g >= 2 && g <= 57) {
            cp8(dB + off, abB + (size_t)(aBase + a) * HW + (g - 2) * WW + w);
        } else {
            *(float2*)(smB + a * AB_CSTR + rr * AB_RSTR + 2 + w) = make_float2(0.f, 0.f);
        }
    }
}

__global__ __launch_bounds__(256, 2) void k_kchange() {
    extern __shared__ __align__(16) float dyn[];
    float* smA = dyn;
    float* smB = dyn + 2 * AM_FLTS;
    __shared__ int sWin[32];
    int atile = blockIdx.x, b = blockIdx.y;
    int tid = threadIdx.x, wid = tid >> 5, lane = tid & 31;
    int gid = lane >> 2, tig = lane & 3;
    if (tid < 32) sWin[tid] = g_fmidx[b * NFM + tid];
    for (int p = tid; p < 2 * AB_FLTS; p += 256) smB[p] = 0.f;
    __syncthreads();
    const float* abB = g_Ab + (size_t)(b * NC) * HW;
    int aBase = atile * 8;
    int cbs[4];
    #pragma unroll
    for (int jt = 0; jt < 4; jt++) {
        int xy = c_xyt[jt * 8 + gid];
        int x = xy / 5, y = xy - x * 5;
        cbs[jt] = (4 - x) * AB_RSTR + (4 - y);
    }
    float d[2][4][4];
    #pragma unroll
    for (int m = 0; m < 2; m++)
        #pragma unroll
        for (int jt = 0; jt < 4; jt++)
            #pragma unroll
            for (int q = 0; q < 4; q++) d[m][jt][q] = 0.f;

    kc_load_chunk(smA, smB, abB, sWin, aBase, 0, tid);
    cp_commit();
    int aOff0 = gid * AM_STRIDE + 2 * tig;
    for (int cc = 0; cc < 14; cc++) {
        int st = cc & 1;
        if (cc + 1 < 14) {
            kc_load_chunk(smA + (st ^ 1) * AM_FLTS, smB + (st ^ 1) * AB_FLTS,
                          abB, sWin, aBase, cc + 1, tid);
            cp_commit();
            asm volatile("cp.async.wait_group 1;" ::: "memory");
        } else {
            asm volatile("cp.async.wait_group 0;" ::: "memory");
        }
        __syncthreads();
        const float* Ax = smA + st * AM_FLTS;
        const float* Bx = smB + st * AB_FLTS + wid * AB_CSTR;
        #pragma unroll
        for (int rl = 0; rl < 4; rl++) {
            #pragma unroll
            for (int ws = 0; ws < 7; ws++) {
                int ao = aOff0 + rl * 56 + ws * 8;
                float2 A0 = *(const float2*)(Ax + ao);
                float2 A1 = *(const float2*)(Ax + ao + 8 * AM_STRIDE);
                float2 A2 = *(const float2*)(Ax + ao + 16 * AM_STRIDE);
                float2 A3 = *(const float2*)(Ax + ao + 24 * AM_STRIDE);
                int bo = rl * AB_RSTR + ws * 8 + 2 * tig;
                #pragma unroll
                for (int jt = 0; jt < 4; jt++) {
                    unsigned b0 = __float_as_uint(Bx[cbs[jt] + bo]);
                    unsigned b1 = __float_as_uint(Bx[cbs[jt] + bo + 1]);
                    mma_tf32(d[0][jt], __float_as_uint(A0.x), __float_as_uint(A1.x),
                             __float_as_uint(A0.y), __float_as_uint(A1.y), b0, b1);
                    mma_tf32(d[1][jt], __float_as_uint(A2.x), __float_as_uint(A3.x),
                             __float_as_uint(A2.y), __float_as_uint(A3.y), b0, b1);
                }
            }
        }
        __syncthreads();
    }
    int aCh = aBase + wid;
    #pragma unroll
    for (int m = 0; m < 2; m++) {
        int c0 = sWin[m * 16 + gid];
        int c1 = sWin[m * 16 + gid + 8];
        #pragma unroll
        for (int jt = 0; jt < 4; jt++) {
            int xyA = c_xyt[jt * 8 + 2 * tig];
            int xyB = c_xyt[jt * 8 + 2 * tig + 1];
            bool vA = (jt < 3) || (tig == 0);
            bool vB = (jt < 3);
            if (vA) {
                atomicAdd(g_Kch + c0 * 3200 + aCh * 25 + xyA, d[m][jt][0]);
                atomicAdd(g_Kch + c1 * 3200 + aCh * 25 + xyA, d[m][jt][2]);
            }
            if (vB) {
                atomicAdd(g_Kch + c0 * 3200 + aCh * 25 + xyB, d[m][jt][1]);
                atomicAdd(g_Kch + c1 * 3200 + aCh * 25 + xyB, d[m][jt][3]);
            }
        }
    }
}

// ---------------- kernel 4: fused combine + gather ----------------
// Block (b, fm): for each ii, normalize pair (o=wl[fm], i=wl[ii]) and write the
// padded 28-col row of g_W2g directly. 8 warps x 4 ii.
__global__ __launch_bounds__(256) void k_wgather(const float* __restrict__ K) {
    __shared__ int wl[32];
    int b = blockIdx.x, fm = blockIdx.y;
    int tid = threadIdx.x, wid = tid >> 5, lane = tid & 31;
    if (tid < 32) wl[tid] = g_fmidx[b * NFM + tid];
    __syncthreads();
    int o = wl[fm];
    bool act = lane < 25;
    float* dstB = g_W2g + ((size_t)(b * NFM + fm) * NFM) * 28;
    #pragma unroll
    for (int pp = 0; pp < 4; pp++) {
        int ii = wid + pp * 8;
        int i = wl[ii];
        const float* kc = g_Kch + (i * NC + o) * 25;
        const float* kk = K + (o * NC + i) * 25;
        float v = act ? kc[lane] * (1.0f / 2048.0f) : 0.f;
        float mn = act ? v : 1e30f, mx = act ? v : -1e30f;
        #pragma unroll
        for (int ofs = 16; ofs; ofs >>= 1) {
            mn = fminf(mn, __shfl_xor_sync(0xffffffffu, mn, ofs));
            mx = fmaxf(mx, __shfl_xor_sync(0xffffffffu, mx, ofs));
        }
        float inv = 1.0f / (mx - mn + 1e-10f);
        float w = act ? 0.9f * kk[lane] + 0.1f * ((v - mn) * inv) : 0.f;
        float mn2 = act ? w : 1e30f, mx2 = act ? w : -1e30f;
        #pragma unroll
        for (int ofs = 16; ofs; ofs >>= 1) {
            mn2 = fminf(mn2, __shfl_xor_sync(0xffffffffu, mn2, ofs));
            mx2 = fmaxf(mx2, __shfl_xor_sync(0xffffffffu, mx2, ofs));
        }
        float inv2 = 1.0f / (mx2 - mn2 + 1e-10f);
        if (lane < 28)
            dstB[ii * 28 + lane] = act ? tf32r((w - mn2) * inv2) : 0.f;
    }
}

// ---------------- kernel 5: L2 conv + output via tf32 mma (2-row chunks, grid 448) ----------------
#define A_STR 40    // == 8 (mod 32): conflict-free float2 A loads; cols 28..39 stay zero
__global__ __launch_bounds__(128, 4) void k_l2mma(float* __restrict__ out) {
    __shared__ float sA[2][32 * A_STR];
    __shared__ __align__(16) float sP[2][360];   // 6 pad rows x 60
    __shared__ int wl[32];
    int q = blockIdx.x, b = blockIdx.y;          // q in 0..27, 2 image rows each
    int tid = threadIdx.x, wid = tid >> 5, lane = tid & 31;
    int gid = lane >> 2, tig = lane & 3;
    if (tid < 32) wl[tid] = g_fmidx[b * NFM + tid];
    for (int p = tid; p < 2 * 32 * A_STR; p += 128) ((float*)sA)[p] = 0.f;
    __syncthreads();

    const float* w2g = g_W2g + (size_t)b * NFM * NFM * 28;
    int offk[4][2];
    #pragma unroll
    for (int ks = 0; ks < 4; ks++) {
        #pragma unroll
        for (int hh = 0; hh < 2; hh++) {
            int xy = ks * 8 + 2 * tig + hh; if (xy > 24) xy = 24;
            int kx = xy / 5, ky = xy - kx * 5;
            offk[ks][hh] = kx * 60 + ky;
        }
    }
    // 14 n-tiles: warp w handles tiles w, w+4, w+8, (w+12 if valid)
    int nT = (wid < 2) ? 4 : 3;
    float acc[4][2][4];
    #pragma unroll
    for (int j = 0; j < 4; j++)
        #pragma unroll
        for (int m = 0; m < 2; m++)
            #pragma unroll
            for (int v = 0; v < 4; v++) acc[j][m][v] = 0.f;

    {   // preload i = 0
        unsigned dA = (unsigned)__cvta_generic_to_shared(&sA[0][0]);
        for (int idx = tid; idx < 224; idx += 128) {
            int m = idx / 7, k7 = idx - m * 7;
            cp16(dA + (unsigned)(m * (A_STR * 4) + k7 * 16),
                 w2g + (size_t)(m * NFM + 0) * 28 + k7 * 4);
        }
        unsigned dP = (unsigned)__cvta_generic_to_shared(&sP[0][0]);
        const float* src = &g_Pad[b][0][0] + q * 120;
        for (int idx = tid; idx < 90; idx += 128)
            cp16(dP + (unsigned)(idx * 16), src + idx * 4);
        cp_commit();
    }
    for (int i = 0; i < 32; i++) {
        int st = i & 1;
        if (i + 1 < 32) {
            unsigned dA = (unsigned)__cvta_generic_to_shared(&sA[st ^ 1][0]);
            for (int idx = tid; idx < 224; idx += 128) {
                int m = idx / 7, k7 = idx - m * 7;
                cp16(dA + (unsigned)(m * (A_STR * 4) + k7 * 16),
                     w2g + (size_t)(m * NFM + i + 1) * 28 + k7 * 4);
            }
            unsigned dP = (unsigned)__cvta_generic_to_shared(&sP[st ^ 1][0]);
            const float* src = &g_Pad[b][i + 1][0] + q * 120;
            for (int idx = tid; idx < 90; idx += 128)
                cp16(dP + (unsigned)(idx * 16), src + idx * 4);
            cp_commit();
            asm volatile("cp.async.wait_group 1;" ::: "memory");
        } else {
            asm volatile("cp.async.wait_group 0;" ::: "memory");
        }
        __syncthreads();
        const float* Ax = &sA[st][0];
        const float* Pz = &sP[st][0];
        unsigned aF[2][4][4];
        #pragma unroll
        for (int mt = 0; mt < 2; mt++)
            #pragma unroll
            for (int ks = 0; ks < 4; ks++) {
                int base = (mt * 16 + gid) * A_STR + ks * 8 + 2 * tig;
                float2 v0 = *(const float2*)(Ax + base);
                float2 v1 = *(const float2*)(Ax + base + 8 * A_STR);
                aF[mt][ks][0] = __float_as_uint(v0.x);
                aF[mt][ks][1] = __float_as_uint(v1.x);
                aF[mt][ks][2] = __float_as_uint(v0.y);
                aF[mt][ks][3] = __float_as_uint(v1.y);
            }
        for (int j = 0; j < nT; j++) {
            int lp = (wid + j * 4) * 8 + gid;      // 0..111
            int r = lp >= 56 ? 1 : 0;
            int base = lp + r * 4;                 // r*60 + (lp - r*56)
            #pragma unroll
            for (int ks = 0; ks < 4; ks++) {
                unsigned b0 = __float_as_uint(Pz[base + offk[ks][0]]);
                unsigned b1 = __float_as_uint(Pz[base + offk[ks][1]]);
                mma_tf32(acc[j][0], aF[0][ks][0], aF[0][ks][1], aF[0][ks][2],
                         aF[0][ks][3], b0, b1);
                mma_tf32(acc[j][1], aF[1][ks][0], aF[1][ks][1], aF[1][ks][2],
                         aF[1][ks][3], b0, b1);
            }
        }
        __syncthreads();
    }
    const float cmul = 0.1f / 32.0f;
    for (int j = 0; j < nT; j++) {
        int p = q * 112 + (wid + j * 4) * 8 + tig * 2;
        #pragma unroll
        for (int mt = 0; mt < 2; mt++) {
            int fm0 = mt * 16 + gid, fm1 = fm0 + 8;
            const float* ab0 = g_Ab + ((size_t)b * NC + wl[fm0]) * HW;
            const float* ab1 = g_Ab + ((size_t)b * NC + wl[fm1]) * HW;
            float* o0 = out + ((size_t)b * NFM + fm0) * HW;
            float* o1 = out + ((size_t)b * NFM + fm1) * HW;
            o0[p]     = ab0[p]     + cmul * acc[j][mt][0];
            o0[p + 1] = ab0[p + 1] + cmul * acc[j][mt][1];
            o1[p]     = ab1[p]     + cmul * acc[j][mt][2];
            o1[p + 1] = ab1[p + 1] + cmul * acc[j][mt][3];
        }
    }
}

extern "C" void kernel_launch(void* const* d_in, const int* in_sizes, int n_in,
                              void* d_out, int out_size) {
    const float* A     = (const float*)d_in[0];
    const float* K     = (const float*)d_in[1];
    const float* noise = (const float*)d_in[2];
    float* out = (float*)d_out;

    cudaFuncSetAttribute(k_kchange, cudaFuncAttributeMaxDynamicSharedMemorySize, KC_SMEM);

    k_ab<<<1024, 256>>>(A, noise);
    k_pad<<<dim3(16, 32), 256>>>();
    k_kchange<<<dim3(16, 16), 256, KC_SMEM>>>();
    k_wgather<<<dim3(16, 32), 256>>>(K);
    k_l2mma<<<dim3(28, 16), 128>>>(out);
}

// round 17
// speedup vs baseline: 1.4134x; 1.0169x over previous
#include <cuda_runtime.h>

#define HH 56
#define WW 56
#define HW 3136
#define NB 16
#define NFM 32
#define NC 128

// ---------------- device scratch ----------------
__device__ float g_Ab[NB * NC * HW];
__device__ float g_sum[NB * NC];
__device__ int   g_fmidx[NB * NFM];
__device__ float g_Kch[NC * NC * 25];
__device__ float g_W2g[NB * NFM * NFM * 28];  // fused combine+gather output, pad to 28
__device__ float g_Pad[NB][NFM][3600];        // padded (60x60) winner channels, tf32-rounded

// bank-engineered n-column -> xy assignment for k_kchange (stride 72):
__device__ const int c_xyt[32] = {
    0, 5, 10, 15, 8, 13, 18, 3,
    1, 6, 11, 16, 9, 14, 19, 4,
    2, 7, 12, 17, 21, 23, 20, 24,
    22, 22, 22, 22, 22, 22, 22, 22};

__device__ __forceinline__ int map2i(int i) { return i < 2 ? 3 - i : (i >= 54 ? 107 - i : i); }
__device__ __forceinline__ int mPad(int i)  { return i < 4 ? 5 - i : (i < 56 ? i - 2 : 109 - i); }

__device__ __forceinline__ float tf32r(float x) {
    float r; asm("cvt.rna.tf32.f32 %0, %1;" : "=f"(r) : "f"(x)); return r;
}
__device__ __forceinline__ void cp8(unsigned dst, const float* src) {
    asm volatile("cp.async.ca.shared.global [%0], [%1], 8;" ::
                 "r"(dst), "l"(__cvta_generic_to_global(src)));
}
__device__ __forceinline__ void cp16(unsigned dst, const float* src) {
    asm volatile("cp.async.cg.shared.global [%0], [%1], 16;" ::
                 "r"(dst), "l"(__cvta_generic_to_global(src)));
}
__device__ __forceinline__ void cp_commit() { asm volatile("cp.async.commit_group;"); }

__device__ __forceinline__ void mma_tf32(float* d, unsigned a0, unsigned a1, unsigned a2,
                                         unsigned a3, unsigned b0, unsigned b1) {
    asm volatile("mma.sync.aligned.m16n8k8.row.col.f32.tf32.tf32.f32 "
                 "{%0,%1,%2,%3}, {%4,%5,%6,%7}, {%8,%9}, {%0,%1,%2,%3};"
                 : "+f"(d[0]), "+f"(d[1]), "+f"(d[2]), "+f"(d[3])
                 : "r"(a0), "r"(a1), "r"(a2), "r"(a3), "r"(b0), "r"(b1));
}

// ---------------- kernel 0: zero K_change (overlaps k_ab on stream 2) ----------------
__global__ void k_zero() { g_Kch[blockIdx.x * 1024 + threadIdx.x] = 0.0f; }

// ---------------- kernel 1: Ab + per-map sums (2 replicas per block) ----------------
__global__ __launch_bounds__(256) void k_ab(const float* __restrict__ A,
                                            const float* __restrict__ noise) {
    __shared__ float sA[HW];
    __shared__ float red[8];
    int bf = blockIdx.x >> 1, half = blockIdx.x & 1;
    int b = bf >> 5, fm = bf & 31;
    const float4* a4 = (const float4*)(A + (size_t)(b * NFM + fm) * HW);
    for (int p = threadIdx.x; p < 784; p += 256) ((float4*)sA)[p] = a4[p];
    __syncthreads();
    for (int r = half * 2; r < half * 2 + 2; r++) {
        int c = r * NFM + fm;
        const float4* n4 = (const float4*)(noise + ((size_t)b * NC + c) * HW);
        float4* o4 = (float4*)(g_Ab + ((size_t)b * NC + c) * HW);
        float s = 0.0f;
        for (int p = threadIdx.x; p < 784; p += 256) {
            float4 nv = n4[p];
            int pix = p * 4;
            int h = (pix * 37450) >> 21;     // pix / 56
            int w = pix - h * WW;
            int hm = map2i(h) * WW;
            float4 v;
            v.x = fmaxf(sA[hm + map2i(w)]     + 0.1f * nv.x, 0.0f);
            v.y = fmaxf(sA[hm + map2i(w + 1)] + 0.1f * nv.y, 0.0f);
            v.z = fmaxf(sA[hm + map2i(w + 2)] + 0.1f * nv.z, 0.0f);
            v.w = fmaxf(sA[hm + map2i(w + 3)] + 0.1f * nv.w, 0.0f);
            o4[p] = v;
            s += v.x + v.y + v.z + v.w;
        }
        #pragma unroll
        for (int o = 16; o; o >>= 1) s += __shfl_xor_sync(0xffffffffu, s, o);
        if ((threadIdx.x & 31) == 0) red[threadIdx.x >> 5] = s;
        __syncthreads();
        if (threadIdx.x == 0) {
            float t = 0.0f;
            #pragma unroll
            for (int i = 0; i < 8; i++) t += red[i];
            g_sum[b * NC + c] = t;
        }
        __syncthreads();
    }
}

// ---------------- kernel 2a: winners only ----------------
__global__ void k_win() {
    int t = threadIdx.x;
    if (t >= NB * NFM) return;
    int b = t >> 5, fm = t & 31;
    const float* s = g_sum + b * NC;
    float best = s[fm];
    int wi = 0;
    #pragma unroll
    for (int r = 1; r < 4; r++) {
        float v = s[r * NFM + fm];
        if (v > best) { best = v; wi = r; }
    }
    g_fmidx[t] = wi * NFM + fm;
}

// ---------------- kernel 2b: padded winner channels (overlaps k_kchange on stream 2) ----------------
__global__ __launch_bounds__(256) void k_padp() {
    int b = blockIdx.x, j = blockIdx.y;
    int c = g_fmidx[b * NFM + j];
    const float* src = g_Ab + (size_t)(b * NC + c) * HW;
    float* dst = &g_Pad[b][j][0];
    for (int p = threadIdx.x; p < 3600; p += 256) {
        int r = p / 60, w = p - r * 60;
        dst[p] = tf32r(src[mPad(r) * WW + mPad(w)]);
    }
}

// ---------------- kernel 3: K_change via tf32 mma.sync (bank-engineered B) ----------------
#define AM_STRIDE 232
#define AM_FLTS  (32 * AM_STRIDE)
#define AB_RSTR  72
#define AB_CSTR  (8 * AB_RSTR)
#define AB_FLTS  (8 * AB_CSTR)
#define KC_SMEM  ((2 * AM_FLTS + 2 * AB_FLTS) * 4)

__device__ __forceinline__ void kc_load_chunk(float* smA, float* smB, const float* abB,
                                              const int* sWin, int aBase, int cc, int tid) {
    unsigned dA = (unsigned)__cvta_generic_to_shared(smA);
    #pragma unroll
    for (int t = 0; t < 7; t++) {
        int idx = tid + t * 256;
        int jr = idx / 14;
        int k = idx - jr * 14;
        int j = jr >> 2, r = jr & 3;
        cp16(dA + (unsigned)(j * (AM_STRIDE * 4) + r * 224 + k * 16),
             abB + (size_t)sWin[j] * HW + (cc * 4 + r) * WW + k * 4);
    }
    unsigned dB = (unsigned)__cvta_generic_to_shared(smB);
    #pragma unroll
    for (int t = 0; t < 7; t++) {
        int idx = tid + t * 256;
        int a = idx / 224;
        int rem = idx - a * 224;
        int rr = rem / 28, w = (rem - rr * 28) * 2;
        int g = cc * 4 + rr;
        unsigned off = (unsigned)((a * AB_CSTR + rr * AB_RSTR + 2 + w) * 4);
        if (g >= 2 && g <= 57) {
            cp8(dB + off, abB + (size_t)(aBase + a) * HW + (g - 2) * WW + w);
        } else {
            *(float2*)(smB + a * AB_CSTR + rr * AB_RSTR + 2 + w) = make_float2(0.f, 0.f);
        }
    }
}

__global__ __launch_bounds__(256, 2) void k_kchange() {
    extern __shared__ __align__(16) float dyn[];
    float* smA = dyn;
    float* smB = dyn + 2 * AM_FLTS;
    __shared__ int sWin[32];
    int atile = blockIdx.x, b = blockIdx.y;
    int tid = threadIdx.x, wid = tid >> 5, lane = tid & 31;
    int gid = lane >> 2, tig = lane & 3;
    if (tid < 32) sWin[tid] = g_fmidx[b * NFM + tid];
    for (int p = tid; p < 2 * AB_FLTS; p += 256) smB[p] = 0.f;
    __syncthreads();
    const float* abB = g_Ab + (size_t)(b * NC) * HW;
    int aBase = atile * 8;
    int cbs[4];
    #pragma unroll
    for (int jt = 0; jt < 4; jt++) {
        int xy = c_xyt[jt * 8 + gid];
        int x = xy / 5, y = xy - x * 5;
        cbs[jt] = (4 - x) * AB_RSTR + (4 - y);
    }
    float d[2][4][4];
    #pragma unroll
    for (int m = 0; m < 2; m++)
        #pragma unroll
        for (int jt = 0; jt < 4; jt++)
            #pragma unroll
            for (int q = 0; q < 4; q++) d[m][jt][q] = 0.f;

    kc_load_chunk(smA, smB, abB, sWin, aBase, 0, tid);
    cp_commit();
    int aOff0 = gid * AM_STRIDE + 2 * tig;
    for (int cc = 0; cc < 14; cc++) {
        int st = cc & 1;
        if (cc + 1 < 14) {
            kc_load_chunk(smA + (st ^ 1) * AM_FLTS, smB + (st ^ 1) * AB_FLTS,
                          abB, sWin, aBase, cc + 1, tid);
            cp_commit();
            asm volatile("cp.async.wait_group 1;" ::: "memory");
        } else {
            asm volatile("cp.async.wait_group 0;" ::: "memory");
        }
        __syncthreads();
        const float* Ax = smA + st * AM_FLTS;
        const float* Bx = smB + st * AB_FLTS + wid * AB_CSTR;
        #pragma unroll
        for (int rl = 0; rl < 4; rl++) {
            #pragma unroll
            for (int ws = 0; ws < 7; ws++) {
                int ao = aOff0 + rl * 56 + ws * 8;
                float2 A0 = *(const float2*)(Ax + ao);
                float2 A1 = *(const float2*)(Ax + ao + 8 * AM_STRIDE);
                float2 A2 = *(const float2*)(Ax + ao + 16 * AM_STRIDE);
                float2 A3 = *(const float2*)(Ax + ao + 24 * AM_STRIDE);
                int bo = rl * AB_RSTR + ws * 8 + 2 * tig;
                #pragma unroll
                for (int jt = 0; jt < 4; jt++) {
                    unsigned b0 = __float_as_uint(Bx[cbs[jt] + bo]);
                    unsigned b1 = __float_as_uint(Bx[cbs[jt] + bo + 1]);
                    mma_tf32(d[0][jt], __float_as_uint(A0.x), __float_as_uint(A1.x),
                             __float_as_uint(A0.y), __float_as_uint(A1.y), b0, b1);
                    mma_tf32(d[1][jt], __float_as_uint(A2.x), __float_as_uint(A3.x),
                             __float_as_uint(A2.y), __float_as_uint(A3.y), b0, b1);
                }
            }
        }
        __syncthreads();
    }
    int aCh = aBase + wid;
    #pragma unroll
    for (int m = 0; m < 2; m++) {
        int c0 = sWin[m * 16 + gid];
        int c1 = sWin[m * 16 + gid + 8];
        #pragma unroll
        for (int jt = 0; jt < 4; jt++) {
            int xyA = c_xyt[jt * 8 + 2 * tig];
            int xyB = c_xyt[jt * 8 + 2 * tig + 1];
            bool vA = (jt < 3) || (tig == 0);
            bool vB = (jt < 3);
            if (vA) {
                atomicAdd(g_Kch + c0 * 3200 + aCh * 25 + xyA, d[m][jt][0]);
                atomicAdd(g_Kch + c1 * 3200 + aCh * 25 + xyA, d[m][jt][2]);
            }
            if (vB) {
                atomicAdd(g_Kch + c0 * 3200 + aCh * 25 + xyB, d[m][jt][1]);
                atomicAdd(g_Kch + c1 * 3200 + aCh * 25 + xyB, d[m][jt][3]);
            }
        }
    }
}

// ---------------- kernel 4: fused combine + gather ----------------
__global__ __launch_bounds__(256) void k_wgather(const float* __restrict__ K) {
    __shared__ int wl[32];
    int b = blockIdx.x, fm = blockIdx.y;
    int tid = threadIdx.x, wid = tid >> 5, lane = tid & 31;
    if (tid < 32) wl[tid] = g_fmidx[b * NFM + tid];
    __syncthreads();
    int o = wl[fm];
    bool act = lane < 25;
    float* dstB = g_W2g + ((size_t)(b * NFM + fm) * NFM) * 28;
    #pragma unroll
    for (int pp = 0; pp < 4; pp++) {
        int ii = wid + pp * 8;
        int i = wl[ii];
        const float* kc = g_Kch + (i * NC + o) * 25;
        const float* kk = K + (o * NC + i) * 25;
        float v = act ? kc[lane] * (1.0f / 2048.0f) : 0.f;
        float mn = act ? v : 1e30f, mx = act ? v : -1e30f;
        #pragma unroll
        for (int ofs = 16; ofs; ofs >>= 1) {
            mn = fminf(mn, __shfl_xor_sync(0xffffffffu, mn, ofs));
            mx = fmaxf(mx, __shfl_xor_sync(0xffffffffu, mx, ofs));
        }
        float inv = 1.0f / (mx - mn + 1e-10f);
        float w = act ? 0.9f * kk[lane] + 0.1f * ((v - mn) * inv) : 0.f;
        float mn2 = act ? w : 1e30f, mx2 = act ? w : -1e30f;
        #pragma unroll
        for (int ofs = 16; ofs; ofs >>= 1) {
            mn2 = fminf(mn2, __shfl_xor_sync(0xffffffffu, mn2, ofs));
            mx2 = fmaxf(mx2, __shfl_xor_sync(0xffffffffu, mx2, ofs));
        }
        float inv2 = 1.0f / (mx2 - mn2 + 1e-10f);
        if (lane < 28)
            dstB[ii * 28 + lane] = act ? tf32r((w - mn2) * inv2) : 0.f;
    }
}

// ---------------- kernel 5: L2 conv + output via tf32 mma (2-row chunks, grid 448) ----------------
#define A_STR 40
__global__ __launch_bounds__(128, 4) void k_l2mma(float* __restrict__ out) {
    __shared__ float sA[2][32 * A_STR];
    __shared__ __align__(16) float sP[2][360];   // 6 pad rows x 60
    __shared__ int wl[32];
    int q = blockIdx.x, b = blockIdx.y;
    int tid = threadIdx.x, wid = tid >> 5, lane = tid & 31;
    int gid = lane >> 2, tig = lane & 3;
    if (tid < 32) wl[tid] = g_fmidx[b * NFM + tid];
    for (int p = tid; p < 2 * 32 * A_STR; p += 128) ((float*)sA)[p] = 0.f;
    __syncthreads();

    const float* w2g = g_W2g + (size_t)b * NFM * NFM * 28;
    int offk[4][2];
    #pragma unroll
    for (int ks = 0; ks < 4; ks++) {
        #pragma unroll
        for (int hh = 0; hh < 2; hh++) {
            int xy = ks * 8 + 2 * tig + hh; if (xy > 24) xy = 24;
            int kx = xy / 5, ky = xy - kx * 5;
            offk[ks][hh] = kx * 60 + ky;
        }
    }
    int nT = (wid < 2) ? 4 : 3;
    float acc[4][2][4];
    #pragma unroll
    for (int j = 0; j < 4; j++)
        #pragma unroll
        for (int m = 0; m < 2; m++)
            #pragma unroll
            for (int v = 0; v < 4; v++) acc[j][m][v] = 0.f;

    {
        unsigned dA = (unsigned)__cvta_generic_to_shared(&sA[0][0]);
        for (int idx = tid; idx < 224; idx += 128) {
            int m = idx / 7, k7 = idx - m * 7;
            cp16(dA + (unsigned)(m * (A_STR * 4) + k7 * 16),
                 w2g + (size_t)(m * NFM + 0) * 28 + k7 * 4);
        }
        unsigned dP = (unsigned)__cvta_generic_to_shared(&sP[0][0]);
        const float* src = &g_Pad[b][0][0] + q * 120;
        for (int idx = tid; idx < 90; idx += 128)
            cp16(dP + (unsigned)(idx * 16), src + idx * 4);
        cp_commit();
    }
    for (int i = 0; i < 32; i++) {
        int st = i & 1;
        if (i + 1 < 32) {
            unsigned dA = (unsigned)__cvta_generic_to_shared(&sA[st ^ 1][0]);
            for (int idx = tid; idx < 224; idx += 128) {
                int m = idx / 7, k7 = idx - m * 7;
                cp16(dA + (unsigned)(m * (A_STR * 4) + k7 * 16),
                     w2g + (size_t)(m * NFM + i + 1) * 28 + k7 * 4);
            }
            unsigned dP = (unsigned)__cvta_generic_to_shared(&sP[st ^ 1][0]);
            const float* src = &g_Pad[b][i + 1][0] + q * 120;
            for (int idx = tid; idx < 90; idx += 128)
                cp16(dP + (unsigned)(idx * 16), src + idx * 4);
            cp_commit();
            asm volatile("cp.async.wait_group 1;" ::: "memory");
        } else {
            asm volatile("cp.async.wait_group 0;" ::: "memory");
        }
        __syncthreads();
        const float* Ax = &sA[st][0];
        const float* Pz = &sP[st][0];
        unsigned aF[2][4][4];
        #pragma unroll
        for (int mt = 0; mt < 2; mt++)
            #pragma unroll
            for (int ks = 0; ks < 4; ks++) {
                int base = (mt * 16 + gid) * A_STR + ks * 8 + 2 * tig;
                float2 v0 = *(const float2*)(Ax + base);
                float2 v1 = *(const float2*)(Ax + base + 8 * A_STR);
                aF[mt][ks][0] = __float_as_uint(v0.x);
                aF[mt][ks][1] = __float_as_uint(v1.x);
                aF[mt][ks][2] = __float_as_uint(v0.y);
                aF[mt][ks][3] = __float_as_uint(v1.y);
            }
        for (int j = 0; j < nT; j++) {
            int lp = (wid + j * 4) * 8 + gid;
            int r = lp >= 56 ? 1 : 0;
            int base = lp + r * 4;
            #pragma unroll
            for (int ks = 0; ks < 4; ks++) {
                unsigned b0 = __float_as_uint(Pz[base + offk[ks][0]]);
                unsigned b1 = __float_as_uint(Pz[base + offk[ks][1]]);
                mma_tf32(acc[j][0], aF[0][ks][0], aF[0][ks][1], aF[0][ks][2],
                         aF[0][ks][3], b0, b1);
                mma_tf32(acc[j][1], aF[1][ks][0], aF[1][ks][1], aF[1][ks][2],
                         aF[1][ks][3], b0, b1);
            }
        }
        __syncthreads();
    }
    const float cmul = 0.1f / 32.0f;
    for (int j = 0; j < nT; j++) {
        int p = q * 112 + (wid + j * 4) * 8 + tig * 2;
        #pragma unroll
        for (int mt = 0; mt < 2; mt++) {
            int fm0 = mt * 16 + gid, fm1 = fm0 + 8;
            const float* ab0 = g_Ab + ((size_t)b * NC + wl[fm0]) * HW;
            const float* ab1 = g_Ab + ((size_t)b * NC + wl[fm1]) * HW;
            float* o0 = out + ((size_t)b * NFM + fm0) * HW;
            float* o1 = out + ((size_t)b * NFM + fm1) * HW;
            o0[p]     = ab0[p]     + cmul * acc[j][mt][0];
            o0[p + 1] = ab0[p + 1] + cmul * acc[j][mt][1];
            o1[p]     = ab1[p]     + cmul * acc[j][mt][2];
            o1[p + 1] = ab1[p + 1] + cmul * acc[j][mt][3];
        }
    }
}

extern "C" void kernel_launch(void* const* d_in, const int* in_sizes, int n_in,
                              void* d_out, int out_size) {
    const float* A     = (const float*)d_in[0];
    const float* K     = (const float*)d_in[1];
    const float* noise = (const float*)d_in[2];
    float* out = (float*)d_out;

    // one-time infra (created on the pre-capture correctness call)
    static cudaStream_t s2 = nullptr;
    static cudaEvent_t e0, ez, e1, e2;
    if (!s2) {
        cudaStreamCreateWithFlags(&s2, cudaStreamNonBlocking);
        cudaEventCreateWithFlags(&e0, cudaEventDisableTiming);
        cudaEventCreateWithFlags(&ez, cudaEventDisableTiming);
        cudaEventCreateWithFlags(&e1, cudaEventDisableTiming);
        cudaEventCreateWithFlags(&e2, cudaEventDisableTiming);
        cudaFuncSetAttribute(k_kchange, cudaFuncAttributeMaxDynamicSharedMemorySize, KC_SMEM);
    }

    // fork: s2 zeroes Kch while main stream builds Ab
    cudaEventRecord(e0, 0);
    cudaStreamWaitEvent(s2, e0, 0);
    k_zero<<<400, 1024, 0, s2>>>();
    cudaEventRecord(ez, s2);

    k_ab<<<1024, 256>>>(A, noise);
    k_win<<<1, 512>>>();
    cudaEventRecord(e1, 0);

    // s2: Pad fill overlaps k_kchange
    cudaStreamWaitEvent(s2, e1, 0);
    k_padp<<<dim3(16, 32), 256, 0, s2>>>();
    cudaEventRecord(e2, s2);

    // main: kchange (needs zeroed Kch)
    cudaStreamWaitEvent(0, ez, 0);
    k_kchange<<<dim3(16, 16), 256, KC_SMEM>>>();

    // join: wgather + l2mma need Kch + Pad
    cudaStreamWaitEvent(0, e2, 0);
    k_wgather<<<dim3(16, 32), 256>>>(K);
    k_l2mma<<<dim3(28, 16), 128>>>(out);
}